// round 10
// baseline (speedup 1.0000x reference)
#include <cuda_runtime.h>
#include <cuda_fp16.h>
#include <math.h>
#include <stdint.h>

// ---------------------------------------------------------------------------
// Problem constants
// ---------------------------------------------------------------------------
#define NTOK 32768
#define TOKD 1024
#define HIDD 1024
#define SEND 256
#define KC   512

// d_out float offsets (flattened reference tuple, fp32)
#define CENT_OFF 0
#define SE_OFF   131072
#define WC_OFF   16908288
#define SCL_OFF  16973824
#define OT_OFF   17039360
#define CT_OFF   17072128
#define OI_OFF   17072640
#define CI_OFF   17105408

#define SCALE_A 16.0f
#define SCALE_B 64.0f
#define OSCALE  (1.0f / 1024.0f)
#define FSCALE  1024.0f          // FFMA-column rescale so shared OSCALE epilogue
                                 // is exact-inverse (power of two -> bit-exact)

// ---------------------------------------------------------------------------
// Scratch (device globals)
// ---------------------------------------------------------------------------
__device__ half  g_xh1[(size_t)NTOK * HIDD];
__device__ half  g_xl1[(size_t)NTOK * HIDD];
__device__ half  g_xh2[(size_t)NTOK * HIDD];
__device__ half  g_xl2[(size_t)NTOK * HIDD];
__device__ float g_tA[(size_t)HIDD * NTOK];   // fp32 activations, K-major
__device__ float g_tB[(size_t)HIDD * NTOK];
__device__ half  g_wh[(size_t)HIDD * HIDD];   // weight hi, N-major
__device__ half  g_wl[(size_t)HIDD * HIDD];   // weight lo, N-major
__device__ float g_c2[KC];
__device__ float g_e2[2 * NTOK];
__device__ int   g_sc[2 * NTOK];
__device__ int   g_counts[2 * KC];
__device__ int   g_offsets[2 * KC];

// ---------------------------------------------------------------------------
// PTX helpers (sm_80-era, portable under compute_100)
// ---------------------------------------------------------------------------
__device__ __forceinline__ uint32_t smem_u32(const void* p) {
    uint32_t a;
    asm("{ .reg .u64 t; cvta.to.shared.u64 t, %1; cvt.u32.u64 %0, t; }"
        : "=r"(a) : "l"(p));
    return a;
}

#define MMA16816(d, a, b) \
    asm volatile( \
        "mma.sync.aligned.m16n8k16.row.col.f32.f16.f16.f32 " \
        "{%0,%1,%2,%3}, {%4,%5,%6,%7}, {%8,%9}, {%0,%1,%2,%3};" \
        : "+f"((d)[0]), "+f"((d)[1]), "+f"((d)[2]), "+f"((d)[3]) \
        : "r"((a)[0]), "r"((a)[1]), "r"((a)[2]), "r"((a)[3]), \
          "r"((b)[0]), "r"((b)[1]))

#define LDMX4(r0, r1, r2, r3, addr) \
    asm volatile("ldmatrix.sync.aligned.m8n8.x4.shared.b16 {%0,%1,%2,%3}, [%4];" \
        : "=r"(r0), "=r"(r1), "=r"(r2), "=r"(r3) : "r"(addr))
#define LDMX2(r0, r1, addr) \
    asm volatile("ldmatrix.sync.aligned.m8n8.x2.shared.b16 {%0,%1}, [%2];" \
        : "=r"(r0), "=r"(r1) : "r"(addr))

#define CPA16(dst, src) \
    asm volatile("cp.async.ca.shared.global [%0], [%1], 16;" :: "r"(dst), "l"(src))
#define CPA_COMMIT() asm volatile("cp.async.commit_group;")
#define CPA_WAIT1()  asm volatile("cp.async.wait_group 1;")
#define CPA_WAIT0()  asm volatile("cp.async.wait_group 0;")

__device__ __forceinline__ void split2(float f, half& h, half& l) {
    h = __float2half_rn(f);
    l = __float2half_rn(f - __half2float(h));
}

// ---------------------------------------------------------------------------
// Hybrid dual-engine GEMM: per 128x128 tile, tensor warps (0-3) compute
// columns 0..79 with fp16x3 split HMMA (operands pre-scaled by 1024 total);
// FFMA warps (4-7) compute columns 80..127 in exact fp32 on RAW operands,
// staged with a x1024 rescale so the shared OSCALE epilogue is exact-inverse.
// One warp of each type per SMSP -> tensor + FMA pipes run concurrently.
// BK=32, 2-stage cp.async pipeline.
// ---------------------------------------------------------------------------
#define S_AH   0          // A hi   128 rows x 80B (64B data + pad)
#define S_AL   10240      // A lo
#define S_BH   20480      // B hi   80 rows x 80B
#define S_BL   26880      // B lo
#define S_A32  33280      // A fp32 K-major: 32 k-rows x 512B
#define S_B32  49664      // B fp32 K-major: 32 k-rows x 192B (48 cols)
#define STAGE_B   55808
#define GEMM_SMEM (2 * STAGE_B)   // 111616
#define CPITCH 132                // epilogue staging pitch (floats)

template<int OUT_SPLIT>
__global__ __launch_bounds__(256, 2)
void gemm_hybrid(const half* __restrict__ AhG, const half* __restrict__ AlG,
                 const float* __restrict__ ATG,   // [Kdim][NTOK] fp32
                 const half* __restrict__ BhG, const half* __restrict__ BlG,
                 const float* __restrict__ WG,    // [Kdim][Mcols] fp32
                 float* __restrict__ Cf,
                 half* __restrict__ Coh, half* __restrict__ Col,
                 float* __restrict__ CT,          // [Mcols][NTOK] fp32
                 int Kdim, int Mcols)
{
    extern __shared__ __align__(16) char smem[];
    const uint32_t sb0 = smem_u32(smem);

    const int tid  = threadIdx.x;
    const int lane = tid & 31, wid = tid >> 5;
    const int blockRow = blockIdx.y << 7;
    const int blockCol = blockIdx.x << 7;

    float acc[80];
#pragma unroll
    for (int i = 0; i < 80; ++i) acc[i] = 0.0f;

    // ---- fill mappings (constant per thread)
    const int fr = tid >> 1, fb = (tid & 1) << 1;
    const half* pAh = AhG + (size_t)(blockRow + fr) * Kdim + fb * 8;
    const half* pAl = AlG + (size_t)(blockRow + fr) * Kdim + fb * 8;
    const half* pBh = BhG + (size_t)(blockCol + (fr < 80 ? fr : 0)) * Kdim + fb * 8;
    const half* pBl = BlG + (size_t)(blockCol + (fr < 80 ? fr : 0)) * Kdim + fb * 8;
    const uint32_t dAB = fr * 80 + fb * 16;

    const int krA = tid >> 3, segA = tid & 7;
    const float* pA32 = ATG + (size_t)krA * NTOK + blockRow + segA * 16;
    const uint32_t dA32 = S_A32 + krA * 512 + segA * 64;

    const int krB = (tid < 192) ? tid / 12 : 0;
    const int ofB = (tid < 192) ? tid % 12 : 0;
    const float* pB32 = WG + (size_t)krB * Mcols + blockCol + 80 + ofB * 4;
    const uint32_t dB32 = S_B32 + krB * 192 + ofB * 16;

    const int chunks = Kdim >> 5;

    auto ISSUE = [&](int c) {
        const uint32_t st = sb0 + (uint32_t)(c & 1) * STAGE_B;
        const int kh = c << 5;
        CPA16(st + S_AH + dAB,      pAh + kh);
        CPA16(st + S_AH + dAB + 16, pAh + kh + 8);
        CPA16(st + S_AL + dAB,      pAl + kh);
        CPA16(st + S_AL + dAB + 16, pAl + kh + 8);
        if (fr < 80 && tid < 160) {
            CPA16(st + S_BH + dAB,      pBh + kh);
            CPA16(st + S_BH + dAB + 16, pBh + kh + 8);
            CPA16(st + S_BL + dAB,      pBl + kh);
            CPA16(st + S_BL + dAB + 16, pBl + kh + 8);
        }
        const float* sA = pA32 + (size_t)kh * NTOK;
        CPA16(st + dA32,      sA);
        CPA16(st + dA32 + 16, sA + 4);
        CPA16(st + dA32 + 32, sA + 8);
        CPA16(st + dA32 + 48, sA + 12);
        if (tid < 192) {
            const float* sB = pB32 + (size_t)kh * Mcols;
            CPA16(st + dB32, sB);
            CPA16(st + dB32 + 16 * 192, sB + (size_t)16 * Mcols);
        }
    };

    // ---- tensor-warp constants
    const int trow0 = (wid & 1) << 6;        // 0 / 64
    const int tcol0 = ((wid >> 1) & 1) * 40; // 0 / 40
    const uint32_t loff  = ((lane & 7) + ((lane >> 3) & 1) * 8) * 80
                         + ((lane >> 4) & 1) * 16;
    const uint32_t loff2 = (lane & 7) * 80 + ((lane >> 3) & 1) * 16;
    const int g = lane >> 2, tig = lane & 3;

    // ---- FFMA-warp constants
    const int fwid = wid - 4;
    const int frow = (fwid & 1) << 6;
    const int fcol = ((fwid >> 1) & 1) * 24;
    const int trow = (lane & 15) << 2;
    const int tcol = (lane >> 4) * 12;

    auto COMPUTE = [&](int s) {
        if (wid < 4) {
            const uint32_t base = sb0 + (uint32_t)s * STAGE_B;
            const uint32_t aH = base + S_AH + trow0 * 80 + loff;
            const uint32_t aL = base + S_AL + trow0 * 80 + loff;
            const uint32_t bHm = base + S_BH + tcol0 * 80;
            const uint32_t bLm = base + S_BL + tcol0 * 80;
#pragma unroll
            for (int ks = 0; ks < 2; ++ks) {
                const uint32_t kof = ks << 5;
                uint32_t ah[4][4], bh[5][2], bl[5][2];
#pragma unroll
                for (int mt = 0; mt < 4; ++mt)
                    LDMX4(ah[mt][0], ah[mt][1], ah[mt][2], ah[mt][3],
                          aH + mt * 1280 + kof);
#pragma unroll
                for (int p = 0; p < 2; ++p) {
                    uint32_t r0, r1, r2, r3;
                    LDMX4(r0, r1, r2, r3, bHm + loff + p * 1280 + kof);
                    bh[2 * p][0] = r0; bh[2 * p + 1][0] = r1;
                    bh[2 * p][1] = r2; bh[2 * p + 1][1] = r3;
                    LDMX4(r0, r1, r2, r3, bLm + loff + p * 1280 + kof);
                    bl[2 * p][0] = r0; bl[2 * p + 1][0] = r1;
                    bl[2 * p][1] = r2; bl[2 * p + 1][1] = r3;
                }
                LDMX2(bh[4][0], bh[4][1], bHm + 2560 + loff2 + kof);
                LDMX2(bl[4][0], bl[4][1], bLm + 2560 + loff2 + kof);
#pragma unroll
                for (int mt = 0; mt < 4; ++mt)
#pragma unroll
                    for (int nt = 0; nt < 5; ++nt)
                        MMA16816(&acc[(mt * 5 + nt) * 4], ah[mt], bh[nt]);
#pragma unroll
                for (int mt = 0; mt < 4; ++mt)
#pragma unroll
                    for (int nt = 0; nt < 5; ++nt)
                        MMA16816(&acc[(mt * 5 + nt) * 4], ah[mt], bl[nt]);
                uint32_t al[4][4];
#pragma unroll
                for (int mt = 0; mt < 4; ++mt)
                    LDMX4(al[mt][0], al[mt][1], al[mt][2], al[mt][3],
                          aL + mt * 1280 + kof);
#pragma unroll
                for (int mt = 0; mt < 4; ++mt)
#pragma unroll
                    for (int nt = 0; nt < 5; ++nt)
                        MMA16816(&acc[(mt * 5 + nt) * 4], al[mt], bh[nt]);
            }
        } else {
            const char* A32 = smem + s * STAGE_B + S_A32 + (frow + trow) * 4;
            const char* B32 = smem + s * STAGE_B + S_B32 + (fcol + tcol) * 4;
#pragma unroll 4
            for (int k = 0; k < 32; ++k) {
                float4 a4 = *reinterpret_cast<const float4*>(A32 + k * 512);
                float4 b0 = *reinterpret_cast<const float4*>(B32 + k * 192);
                float4 b1 = *reinterpret_cast<const float4*>(B32 + k * 192 + 16);
                float4 b2 = *reinterpret_cast<const float4*>(B32 + k * 192 + 32);
                float a[4] = {a4.x, a4.y, a4.z, a4.w};
                float b[12] = {b0.x, b0.y, b0.z, b0.w, b1.x, b1.y,
                               b1.z, b1.w, b2.x, b2.y, b2.z, b2.w};
#pragma unroll
                for (int i = 0; i < 4; ++i)
#pragma unroll
                    for (int j = 0; j < 12; ++j)
                        acc[i * 12 + j] = fmaf(a[i], b[j], acc[i * 12 + j]);
            }
        }
    };

    ISSUE(0);
    CPA_COMMIT();
    for (int c = 0; c < chunks; ++c) {
        if (c + 1 < chunks) {
            ISSUE(c + 1);
            CPA_COMMIT();
            CPA_WAIT1();
        } else {
            CPA_WAIT0();
        }
        __syncthreads();
        COMPUTE(c & 1);
        __syncthreads();
    }

    // ---- epilogue: stage fp32 tile in smem
    float* cst = reinterpret_cast<float*>(smem);
    if (wid < 4) {
#pragma unroll
        for (int mt = 0; mt < 4; ++mt)
#pragma unroll
            for (int nt = 0; nt < 5; ++nt) {
                const float* a4 = &acc[(mt * 5 + nt) * 4];
                int r0 = trow0 + (mt << 4) + g;
                int cc = tcol0 + (nt << 3) + (tig << 1);
                cst[r0 * CPITCH + cc]           = a4[0];
                cst[r0 * CPITCH + cc + 1]       = a4[1];
                cst[(r0 + 8) * CPITCH + cc]     = a4[2];
                cst[(r0 + 8) * CPITCH + cc + 1] = a4[3];
            }
    } else {
        // FIX (round 9 bug): FFMA operands are unscaled, tensor operands carry
        // x1024; rescale FFMA accs so the shared OSCALE epilogue is exact-inverse.
#pragma unroll
        for (int i = 0; i < 4; ++i)
#pragma unroll
            for (int j = 0; j < 12; ++j)
                cst[(frow + trow + i) * CPITCH + 80 + fcol + tcol + j] =
                    acc[i * 12 + j] * FSCALE;
    }
    __syncthreads();

    // pass 1: tanh, write primary outputs, write tanh back into cst
    {
        const int row  = tid >> 1;
        const int colh = (tid & 1) << 6;
        float* src = cst + row * CPITCH + colh;
        const size_t gb = (size_t)(blockRow + row) * Mcols + blockCol + colh;
#pragma unroll
        for (int j = 0; j < 16; ++j) {
            float4 v = *reinterpret_cast<const float4*>(src + (j << 2));
            float t0 = tanhf(v.x * OSCALE), t1 = tanhf(v.y * OSCALE);
            float t2 = tanhf(v.z * OSCALE), t3 = tanhf(v.w * OSCALE);
            if (OUT_SPLIT) {
                half h0, h1, h2, h3, l0, l1, l2, l3;
                split2(t0 * SCALE_A, h0, l0); split2(t1 * SCALE_A, h1, l1);
                split2(t2 * SCALE_A, h2, l2); split2(t3 * SCALE_A, h3, l3);
                half2 ph0 = __halves2half2(h0, h1), ph1 = __halves2half2(h2, h3);
                half2 pl0 = __halves2half2(l0, l1), pl1 = __halves2half2(l2, l3);
                uint2 uh, ul;
                uh.x = reinterpret_cast<uint32_t&>(ph0);
                uh.y = reinterpret_cast<uint32_t&>(ph1);
                ul.x = reinterpret_cast<uint32_t&>(pl0);
                ul.y = reinterpret_cast<uint32_t&>(pl1);
                *reinterpret_cast<uint2*>(Coh + gb + (j << 2)) = uh;
                *reinterpret_cast<uint2*>(Col + gb + (j << 2)) = ul;
                float4 o; o.x = t0; o.y = t1; o.z = t2; o.w = t3;
                *reinterpret_cast<float4*>(src + (j << 2)) = o;   // back into cst
            } else {
                float4 o; o.x = t0; o.y = t1; o.z = t2; o.w = t3;
                *reinterpret_cast<float4*>(Cf + gb + (j << 2)) = o;
            }
        }
    }

    // pass 2 (OUT_SPLIT only): transposed fp32 store for next layer's FFMA A
    if (OUT_SPLIT) {
        __syncthreads();
        const int c  = tid >> 1;
        const int hh = (tid & 1) << 6;
        float* dst = CT + (size_t)(blockCol + c) * NTOK + blockRow + hh;
#pragma unroll
        for (int j = 0; j < 16; ++j) {
            float4 o;
            o.x = cst[(hh + 4 * j + 0) * CPITCH + c];
            o.y = cst[(hh + 4 * j + 1) * CPITCH + c];
            o.z = cst[(hh + 4 * j + 2) * CPITCH + c];
            o.w = cst[(hh + 4 * j + 3) * CPITCH + c];
            *reinterpret_cast<float4*>(dst + 4 * j) = o;
        }
    }
}

// ---------------------------------------------------------------------------
// emb fp32 -> (hi, lo) halves, scaled
// ---------------------------------------------------------------------------
__global__ void split_src(const float* __restrict__ X,
                          half* __restrict__ Xh, half* __restrict__ Xl)
{
    int i = blockIdx.x * blockDim.x + threadIdx.x;
    float4 v = reinterpret_cast<const float4*>(X)[i];
    half h0, h1, h2, h3, l0, l1, l2, l3;
    split2(v.x * SCALE_A, h0, l0); split2(v.y * SCALE_A, h1, l1);
    split2(v.z * SCALE_A, h2, l2); split2(v.w * SCALE_A, h3, l3);
    half2 ph0 = __halves2half2(h0, h1), ph1 = __halves2half2(h2, h3);
    half2 pl0 = __halves2half2(l0, l1), pl1 = __halves2half2(l2, l3);
    uint2 uh, ul;
    uh.x = reinterpret_cast<uint32_t&>(ph0); uh.y = reinterpret_cast<uint32_t&>(ph1);
    ul.x = reinterpret_cast<uint32_t&>(pl0); ul.y = reinterpret_cast<uint32_t&>(pl1);
    reinterpret_cast<uint2*>(Xh)[i] = uh;
    reinterpret_cast<uint2*>(Xl)[i] = ul;
}

// X[NTOK][D] -> XT[D][NTOK] fp32
__global__ void transpose_f32(const float* __restrict__ X, float* __restrict__ XT,
                              int D)
{
    __shared__ float t[32][33];
    const int bx = blockIdx.x << 5;   // dim base
    const int by = blockIdx.y << 5;   // token base
#pragma unroll
    for (int j = 0; j < 32; j += 8)
        t[threadIdx.y + j][threadIdx.x] =
            X[(size_t)(by + threadIdx.y + j) * D + bx + threadIdx.x];
    __syncthreads();
#pragma unroll
    for (int j = 0; j < 32; j += 8)
        XT[(size_t)(bx + threadIdx.y + j) * NTOK + by + threadIdx.x] =
            t[threadIdx.x][threadIdx.y + j];
}

// W[K,N] fp32 -> Th/Tl[N,K] halves, scaled
__global__ void transpose_split(const float* __restrict__ W,
                                half* __restrict__ Th, half* __restrict__ Tl,
                                int K, int N)
{
    __shared__ float t[32][33];
    const int bx = blockIdx.x << 5;
    const int by = blockIdx.y << 5;
#pragma unroll
    for (int j = 0; j < 32; j += 8)
        t[threadIdx.y + j][threadIdx.x] =
            W[(size_t)(by + threadIdx.y + j) * N + bx + threadIdx.x];
    __syncthreads();
#pragma unroll
    for (int j = 0; j < 32; j += 8) {
        float f = t[threadIdx.x][threadIdx.y + j] * SCALE_B;
        half h, l;
        split2(f, h, l);
        size_t o = (size_t)(bx + threadIdx.y + j) * K + by + threadIdx.x;
        Th[o] = h;
        Tl[o] = l;
    }
}

// ---------------------------------------------------------------------------
// centroids / sumsq
// ---------------------------------------------------------------------------
__global__ void centroid_tanh(const float* __restrict__ raw, float* __restrict__ out)
{
    int i = blockIdx.x * blockDim.x + threadIdx.x;
    out[CENT_OFF + i] = tanhf(raw[i]);
}

__global__ void c2_kernel(const float* __restrict__ cent)
{
    int w    = (blockIdx.x * blockDim.x + threadIdx.x) >> 5;
    int lane = threadIdx.x & 31;
    if (w >= KC) return;
    const float* row = cent + (size_t)w * SEND;
    float s = 0.0f;
#pragma unroll
    for (int j = 0; j < 8; ++j) { float v = row[lane + j * 32]; s = fmaf(v, v, s); }
#pragma unroll
    for (int o = 16; o > 0; o >>= 1) s += __shfl_xor_sync(0xffffffffu, s, o);
    if (lane == 0) g_c2[w] = s;
}

__global__ void e2_kernel(const float* __restrict__ SE, int modal)
{
    int w    = (blockIdx.x * blockDim.x + threadIdx.x) >> 5;
    int lane = threadIdx.x & 31;
    const float* row = SE + (size_t)w * SEND;
    float s = 0.0f;
#pragma unroll
    for (int j = 0; j < 8; ++j) { float v = row[lane + j * 32]; s = fmaf(v, v, s); }
#pragma unroll
    for (int o = 16; o > 0; o >>= 1) s += __shfl_xor_sync(0xffffffffu, s, o);
    if (lane == 0) g_e2[modal * NTOK + w] = s;
}

// ---------------------------------------------------------------------------
// Assignment (exact fp32; unchanged from round 3)
// ---------------------------------------------------------------------------
__global__ __launch_bounds__(256)
void assign_kernel(const float* __restrict__ SE, const float* __restrict__ CENT,
                   int modal)
{
    __shared__ float As[16][132];
    __shared__ float Bs[16][132];
    __shared__ float rv[128][16];
    __shared__ int   ri[128][16];

    const int tid = threadIdx.x;
    const int tx  = tid & 15, ty = tid >> 4;
    const int rowBase = blockIdx.x << 7;

    const int lr  = tid >> 2;
    const int lc4 = (tid & 3) << 2;

    float e2r[8];
#pragma unroll
    for (int i = 0; i < 8; ++i)
        e2r[i] = g_e2[modal * NTOK + rowBase + (ty << 3) + i];

    float bestV[8]; int bestI[8];
#pragma unroll
    for (int i = 0; i < 8; ++i) { bestV[i] = 3.4e38f; bestI[i] = 0; }

    for (int ct = 0; ct < KC; ct += 128) {
        float acc[8][8];
#pragma unroll
        for (int i = 0; i < 8; ++i)
#pragma unroll
            for (int j = 0; j < 8; ++j) acc[i][j] = 0.0f;

        for (int kt = 0; kt < SEND; kt += 16) {
#pragma unroll
            for (int l = 0; l < 2; ++l) {
                int r = lr + l * 64;
                float4 va = *reinterpret_cast<const float4*>(
                    SE + (size_t)(rowBase + r) * SEND + kt + lc4);
                As[lc4 + 0][r] = va.x; As[lc4 + 1][r] = va.y;
                As[lc4 + 2][r] = va.z; As[lc4 + 3][r] = va.w;
                float4 vb = *reinterpret_cast<const float4*>(
                    CENT + (size_t)(ct + r) * SEND + kt + lc4);
                Bs[lc4 + 0][r] = vb.x; Bs[lc4 + 1][r] = vb.y;
                Bs[lc4 + 2][r] = vb.z; Bs[lc4 + 3][r] = vb.w;
            }
            __syncthreads();
#pragma unroll
            for (int k = 0; k < 16; ++k) {
                float a[8], b[8];
#pragma unroll
                for (int i = 0; i < 8; ++i) a[i] = As[k][(ty << 3) + i];
#pragma unroll
                for (int j = 0; j < 8; ++j) b[j] = Bs[k][(tx << 3) + j];
#pragma unroll
                for (int i = 0; i < 8; ++i)
#pragma unroll
                    for (int j = 0; j < 8; ++j)
                        acc[i][j] = fmaf(a[i], b[j], acc[i][j]);
            }
            __syncthreads();
        }

        float c2v[8];
#pragma unroll
        for (int j = 0; j < 8; ++j) c2v[j] = g_c2[ct + (tx << 3) + j];
#pragma unroll
        for (int i = 0; i < 8; ++i)
#pragma unroll
            for (int j = 0; j < 8; ++j) {
                int col = ct + (tx << 3) + j;
                float s = (c2v[j] + e2r[i]) - 2.0f * acc[i][j];
                if (s < bestV[i] || (s == bestV[i] && col < bestI[i])) {
                    bestV[i] = s; bestI[i] = col;
                }
            }
    }

#pragma unroll
    for (int i = 0; i < 8; ++i) {
        rv[(ty << 3) + i][tx] = bestV[i];
        ri[(ty << 3) + i][tx] = bestI[i];
    }
    __syncthreads();
    if (tid < 128) {
        float bv = rv[tid][0]; int bi = ri[tid][0];
#pragma unroll
        for (int t = 1; t < 16; ++t) {
            float v = rv[tid][t]; int ix = ri[tid][t];
            if (v < bv || (v == bv && ix < bi)) { bv = v; bi = ix; }
        }
        g_sc[modal * NTOK + rowBase + tid] = bi;
    }
}

// ---------------------------------------------------------------------------
// Counting sort (stable)
// ---------------------------------------------------------------------------
__global__ void zero_counts()
{
    int i = blockIdx.x * blockDim.x + threadIdx.x;
    if (i < 2 * KC) g_counts[i] = 0;
}

__global__ void count_kernel(int modal)
{
    int i = blockIdx.x * blockDim.x + threadIdx.x;
    atomicAdd(&g_counts[modal * KC + g_sc[modal * NTOK + i]], 1);
}

__global__ void scan_kernel(int modal)
{
    __shared__ int tmp[KC];
    int t = threadIdx.x;
    int v = g_counts[modal * KC + t];
    tmp[t] = v;
    __syncthreads();
    for (int off = 1; off < KC; off <<= 1) {
        int x = (t >= off) ? tmp[t - off] : 0;
        __syncthreads();
        tmp[t] += x;
        __syncthreads();
    }
    g_offsets[modal * KC + t] = tmp[t] - v;
}

__global__ void scatter_kernel(int modal, float* __restrict__ order)
{
    const int k = blockIdx.x;
    const int base0 = modal * NTOK;
    __shared__ int warpTot[8];
    int base = g_offsets[modal * KC + k];
    int lane = threadIdx.x & 31, wid = threadIdx.x >> 5;

    for (int start = 0; start < NTOK; start += 256) {
        int i = start + threadIdx.x;
        bool m = (g_sc[base0 + i] == k);
        unsigned b = __ballot_sync(0xffffffffu, m);
        if (lane == 0) warpTot[wid] = __popc(b);
        __syncthreads();
        int woff = 0, tot = 0;
#pragma unroll
        for (int w = 0; w < 8; ++w) { int c = warpTot[w]; tot += c; if (w < wid) woff += c; }
        if (m) order[base + woff + __popc(b & ((1u << lane) - 1u))] = (float)i;
        base += tot;
        __syncthreads();
    }
}

// ---------------------------------------------------------------------------
// word_class / sense_class / counts
// ---------------------------------------------------------------------------
__global__ void finalize_kernel(float* __restrict__ out)
{
    int i = blockIdx.x * blockDim.x + threadIdx.x;
    out[WC_OFF + i]  = (i < NTOK) ? 0.0f : 1.0f;
    out[SCL_OFF + i] = (float)g_sc[i];
}

__global__ void counts_out_kernel(float* __restrict__ out)
{
    int i = blockIdx.x * blockDim.x + threadIdx.x;
    if (i < 2 * KC) {
        int m = i >> 9, k = i & 511;
        out[(m ? CI_OFF : CT_OFF) + k] = (float)g_counts[i];
    }
}

// ---------------------------------------------------------------------------
// Launch
// ---------------------------------------------------------------------------
extern "C" void kernel_launch(void* const* d_in, const int* in_sizes, int n_in,
                              void* d_out, int out_size)
{
    const float* emb[2] = { (const float*)d_in[0], (const float*)d_in[1] };
    const float* W1[2]  = { (const float*)d_in[2], (const float*)d_in[5] };
    const float* W2[2]  = { (const float*)d_in[3], (const float*)d_in[6] };
    const float* W3[2]  = { (const float*)d_in[4], (const float*)d_in[7] };
    const float* craw   = (const float*)d_in[8];
    float* out = (float*)d_out;

    half *xh1, *xl1, *xh2, *xl2, *wh, *wl;
    float *tA, *tB;
    cudaGetSymbolAddress((void**)&xh1, g_xh1);
    cudaGetSymbolAddress((void**)&xl1, g_xl1);
    cudaGetSymbolAddress((void**)&xh2, g_xh2);
    cudaGetSymbolAddress((void**)&xl2, g_xl2);
    cudaGetSymbolAddress((void**)&wh, g_wh);
    cudaGetSymbolAddress((void**)&wl, g_wl);
    cudaGetSymbolAddress((void**)&tA, g_tA);
    cudaGetSymbolAddress((void**)&tB, g_tB);

    cudaFuncSetAttribute(gemm_hybrid<0>,
                         cudaFuncAttributeMaxDynamicSharedMemorySize, GEMM_SMEM);
    cudaFuncSetAttribute(gemm_hybrid<1>,
                         cudaFuncAttributeMaxDynamicSharedMemorySize, GEMM_SMEM);

    centroid_tanh<<<(KC * SEND) / 256, 256>>>(craw, out);
    c2_kernel<<<(KC * 32) / 256, 256>>>(out + CENT_OFF);
    zero_counts<<<4, 256>>>();

    for (int m = 0; m < 2; ++m) {
        float* se = out + SE_OFF + (size_t)m * NTOK * SEND;

        split_src<<<(NTOK * TOKD / 4) / 256, 256>>>(emb[m], xh1, xl1);
        transpose_f32<<<dim3(TOKD / 32, NTOK / 32), dim3(32, 8)>>>(emb[m], tA, TOKD);

        transpose_split<<<dim3(HIDD / 32, TOKD / 32), dim3(32, 8)>>>(W1[m], wh, wl, TOKD, HIDD);
        gemm_hybrid<1><<<dim3(HIDD / 128, NTOK / 128), 256, GEMM_SMEM>>>(
            xh1, xl1, tA, wh, wl, W1[m], nullptr, xh2, xl2, tB, TOKD, HIDD);

        transpose_split<<<dim3(HIDD / 32, HIDD / 32), dim3(32, 8)>>>(W2[m], wh, wl, HIDD, HIDD);
        gemm_hybrid<1><<<dim3(HIDD / 128, NTOK / 128), 256, GEMM_SMEM>>>(
            xh2, xl2, tB, wh, wl, W2[m], nullptr, xh1, xl1, tA, HIDD, HIDD);

        transpose_split<<<dim3(SEND / 32, HIDD / 32), dim3(32, 8)>>>(W3[m], wh, wl, HIDD, SEND);
        gemm_hybrid<0><<<dim3(SEND / 128, NTOK / 128), 256, GEMM_SMEM>>>(
            xh1, xl1, tA, wh, wl, W3[m], se, nullptr, nullptr, nullptr, HIDD, SEND);

        e2_kernel<<<(NTOK * 32) / 256, 256>>>(se, m);
        assign_kernel<<<NTOK / 128, 256>>>(se, out + CENT_OFF, m);

        count_kernel<<<NTOK / 256, 256>>>(m);
        scan_kernel<<<1, KC>>>(m);
        scatter_kernel<<<KC, 256>>>(m, out + (m ? OI_OFF : OT_OFF));
    }

    finalize_kernel<<<(2 * NTOK) / 256, 256>>>(out);
    counts_out_kernel<<<4, 256>>>(out);
}

// round 11
// speedup vs baseline: 1.9551x; 1.9551x over previous
#include <cuda_runtime.h>
#include <cuda_fp16.h>
#include <math.h>
#include <stdint.h>

// ---------------------------------------------------------------------------
// Problem constants
// ---------------------------------------------------------------------------
#define NTOK 32768
#define TOKD 1024
#define HIDD 1024
#define SEND 256
#define KC   512

// d_out float offsets (flattened reference tuple, fp32)
#define CENT_OFF 0
#define SE_OFF   131072
#define WC_OFF   16908288
#define SCL_OFF  16973824
#define OT_OFF   17039360
#define CT_OFF   17072128
#define OI_OFF   17072640
#define CI_OFF   17105408

#define SCALE_A 16.0f
#define SCALE_B 64.0f
#define OSCALE  (1.0f / 1024.0f)

// ---------------------------------------------------------------------------
// Scratch (device globals)
// ---------------------------------------------------------------------------
__device__ half  g_xh1[(size_t)NTOK * HIDD];
__device__ half  g_xl1[(size_t)NTOK * HIDD];
__device__ half  g_xh2[(size_t)NTOK * HIDD];
__device__ half  g_xl2[(size_t)NTOK * HIDD];
__device__ half  g_wh[(size_t)HIDD * HIDD];    // weight hi (transposed, N-major)
__device__ half  g_wl[(size_t)HIDD * HIDD];    // weight lo
__device__ half  g_ch[(size_t)KC * SEND];      // centroids hi (x64)
__device__ half  g_cl[(size_t)KC * SEND];      // centroids lo
__device__ float g_c2[KC];
__device__ float g_e2[2 * NTOK];
__device__ int   g_sc[2 * NTOK];
__device__ int   g_counts[2 * KC];
__device__ int   g_offsets[2 * KC];

// ---------------------------------------------------------------------------
// PTX helpers (sm_80-era, portable under compute_100)
// ---------------------------------------------------------------------------
__device__ __forceinline__ uint32_t smem_u32(const void* p) {
    uint32_t a;
    asm("{ .reg .u64 t; cvta.to.shared.u64 t, %1; cvt.u32.u64 %0, t; }"
        : "=r"(a) : "l"(p));
    return a;
}

#define MMA16816(d, a, b) \
    asm volatile( \
        "mma.sync.aligned.m16n8k16.row.col.f32.f16.f16.f32 " \
        "{%0,%1,%2,%3}, {%4,%5,%6,%7}, {%8,%9}, {%0,%1,%2,%3};" \
        : "+f"((d)[0]), "+f"((d)[1]), "+f"((d)[2]), "+f"((d)[3]) \
        : "r"((a)[0]), "r"((a)[1]), "r"((a)[2]), "r"((a)[3]), \
          "r"((b)[0]), "r"((b)[1]))

#define LDMX4(r0, r1, r2, r3, addr) \
    asm volatile("ldmatrix.sync.aligned.m8n8.x4.shared.b16 {%0,%1,%2,%3}, [%4];" \
        : "=r"(r0), "=r"(r1), "=r"(r2), "=r"(r3) : "r"(addr))

#define CPA16(dst, src) \
    asm volatile("cp.async.ca.shared.global [%0], [%1], 16;" :: "r"(dst), "l"(src))
#define CPA_COMMIT() asm volatile("cp.async.commit_group;")
#define CPA_WAIT1()  asm volatile("cp.async.wait_group 1;")
#define CPA_WAIT0()  asm volatile("cp.async.wait_group 0;")

__device__ __forceinline__ void split2(float f, half& h, half& l) {
    h = __float2half_rn(f);
    l = __float2half_rn(f - __half2float(h));
}

// ---------------------------------------------------------------------------
// fp16x3 split-GEMM (round-7 proven kernel).
//   acc = Ah*Bh + Ah*Bl + Al*Bh (fp32);  out = tanh(acc * OSCALE)
// Tile 128x128, BK=32, 2-stage cp.async pipeline, ldmatrix fragments,
// pitch-40-half smem rows (conflict-free fills + ldmatrix).
// OMODE: 0 = fp32 out; 1 = split (hi,lo)*SCALE_A out; 2 = fp32 out + split out.
// ---------------------------------------------------------------------------
#define TILE_B    10240         // 128 rows * 80 B
#define STAGE_B   40960         // Ah | Al | Bh | Bl tiles
#define GEMM_SMEM 81920         // 2 stages

template<int OMODE>
__global__ __launch_bounds__(256)
void gemm_split(const half* __restrict__ Ah, const half* __restrict__ Al,
                const half* __restrict__ Bh, const half* __restrict__ Bl,
                float* __restrict__ Cf,
                half* __restrict__ Coh, half* __restrict__ Col,
                int Kdim, int Mcols)
{
    extern __shared__ __align__(16) char smem[];
    const uint32_t sb0 = smem_u32(smem);

    const int tid  = threadIdx.x;
    const int lane = tid & 31, wid = tid >> 5;
    const int warpRow = wid >> 2;           // 0..1  -> 64-row band
    const int warpCol = wid & 3;            // 0..3  -> 32-col band
    const int g = lane >> 2, tig = lane & 3;
    const int blockRow = blockIdx.y << 7;
    const int blockCol = blockIdx.x << 7;

    float acc[64];
#pragma unroll
    for (int i = 0; i < 64; ++i) acc[i] = 0.0f;

    // cp.async fill: thread -> (row, two 16B blocks)
    const int fr = tid >> 1;               // 0..127
    const int fb = (tid & 1) << 1;         // 0 or 2
    const half* srcA  = Ah + (size_t)(blockRow + fr) * Kdim + fb * 8;
    const half* srcAl = Al + (size_t)(blockRow + fr) * Kdim + fb * 8;
    const half* srcB  = Bh + (size_t)(blockCol + fr) * Kdim + fb * 8;
    const half* srcBl = Bl + (size_t)(blockCol + fr) * Kdim + fb * 8;
    const uint32_t dstBase = sb0 + fr * 80 + fb * 16;

    const uint32_t loff = (uint32_t)(((lane & 7) + ((lane >> 3) & 1) * 8) * 80
                                     + ((lane >> 4) & 1) * 16);

    const int chunks = Kdim >> 5;

    auto ISSUE = [&](int c) {
        const int s = c & 1;
        const int kh = c << 5;
        uint32_t d = dstBase + s * STAGE_B;
        CPA16(d,              srcA + kh);  CPA16(d + 16,              srcA + kh + 8);
        CPA16(d + TILE_B,     srcAl + kh); CPA16(d + TILE_B + 16,     srcAl + kh + 8);
        CPA16(d + 2 * TILE_B, srcB + kh);  CPA16(d + 2 * TILE_B + 16, srcB + kh + 8);
        CPA16(d + 3 * TILE_B, srcBl + kh); CPA16(d + 3 * TILE_B + 16, srcBl + kh + 8);
    };

    auto COMPUTE = [&](int s) {
        const uint32_t base  = sb0 + s * STAGE_B;
        const uint32_t aBase = base + (warpRow * 64) * 80 + loff;
        const uint32_t bBase = base + 2 * TILE_B + (warpCol * 32) * 80 + loff;
#pragma unroll
        for (int ks = 0; ks < 2; ++ks) {
            const uint32_t kof = ks << 5;
            uint32_t ah[4][4], al[4][4], bh[4][2], bl[4][2];
#pragma unroll
            for (int mt = 0; mt < 4; ++mt) {
                uint32_t ad = aBase + mt * (16 * 80) + kof;
                LDMX4(ah[mt][0], ah[mt][1], ah[mt][2], ah[mt][3], ad);
                LDMX4(al[mt][0], al[mt][1], al[mt][2], al[mt][3], ad + TILE_B);
            }
#pragma unroll
            for (int p = 0; p < 2; ++p) {
                uint32_t bd = bBase + p * (16 * 80) + kof;
                uint32_t r0, r1, r2, r3;
                LDMX4(r0, r1, r2, r3, bd);
                bh[2 * p][0] = r0; bh[2 * p + 1][0] = r1;
                bh[2 * p][1] = r2; bh[2 * p + 1][1] = r3;
                LDMX4(r0, r1, r2, r3, bd + TILE_B);
                bl[2 * p][0] = r0; bl[2 * p + 1][0] = r1;
                bl[2 * p][1] = r2; bl[2 * p + 1][1] = r3;
            }
#pragma unroll
            for (int mt = 0; mt < 4; ++mt)
#pragma unroll
                for (int nt = 0; nt < 4; ++nt)
                    MMA16816(&acc[(mt * 4 + nt) * 4], ah[mt], bh[nt]);
#pragma unroll
            for (int mt = 0; mt < 4; ++mt)
#pragma unroll
                for (int nt = 0; nt < 4; ++nt)
                    MMA16816(&acc[(mt * 4 + nt) * 4], ah[mt], bl[nt]);
#pragma unroll
            for (int mt = 0; mt < 4; ++mt)
#pragma unroll
                for (int nt = 0; nt < 4; ++nt)
                    MMA16816(&acc[(mt * 4 + nt) * 4], al[mt], bh[nt]);
        }
    };

    ISSUE(0);
    CPA_COMMIT();
    for (int c = 0; c < chunks; ++c) {
        if (c + 1 < chunks) {
            ISSUE(c + 1);
            CPA_COMMIT();
            CPA_WAIT1();
        } else {
            CPA_WAIT0();
        }
        __syncthreads();
        COMPUTE(c & 1);
        __syncthreads();
    }

    // ---- epilogue: stage fp32 acc in smem, then coalesced transform+store
    float* cst = reinterpret_cast<float*>(smem);   // [128][132]
#pragma unroll
    for (int mt = 0; mt < 4; ++mt)
#pragma unroll
        for (int nt = 0; nt < 4; ++nt) {
            const float* a4 = &acc[(mt * 4 + nt) * 4];
            int r0 = (warpRow << 6) + (mt << 4) + g;
            int cc = (warpCol << 5) + (nt << 3) + (tig << 1);
            *reinterpret_cast<float2*>(cst + r0 * 132 + cc) =
                make_float2(a4[0], a4[1]);
            *reinterpret_cast<float2*>(cst + (r0 + 8) * 132 + cc) =
                make_float2(a4[2], a4[3]);
        }
    __syncthreads();
    {
        const int row  = tid >> 1;
        const int colh = (tid & 1) << 6;
        const float* src = cst + row * 132 + colh;
        const size_t gb = (size_t)(blockRow + row) * Mcols + blockCol + colh;
#pragma unroll
        for (int j = 0; j < 16; ++j) {
            float4 v = *reinterpret_cast<const float4*>(src + (j << 2));
            float t0 = tanhf(v.x * OSCALE), t1 = tanhf(v.y * OSCALE);
            float t2 = tanhf(v.z * OSCALE), t3 = tanhf(v.w * OSCALE);
            if (OMODE >= 1) {
                half h0, h1, h2, h3, l0, l1, l2, l3;
                split2(t0 * SCALE_A, h0, l0); split2(t1 * SCALE_A, h1, l1);
                split2(t2 * SCALE_A, h2, l2); split2(t3 * SCALE_A, h3, l3);
                half2 ph0 = __halves2half2(h0, h1), ph1 = __halves2half2(h2, h3);
                half2 pl0 = __halves2half2(l0, l1), pl1 = __halves2half2(l2, l3);
                uint2 uh, ul;
                uh.x = reinterpret_cast<uint32_t&>(ph0);
                uh.y = reinterpret_cast<uint32_t&>(ph1);
                ul.x = reinterpret_cast<uint32_t&>(pl0);
                ul.y = reinterpret_cast<uint32_t&>(pl1);
                *reinterpret_cast<uint2*>(Coh + gb + (j << 2)) = uh;
                *reinterpret_cast<uint2*>(Col + gb + (j << 2)) = ul;
            }
            if (OMODE != 1) {
                float4 o; o.x = t0; o.y = t1; o.z = t2; o.w = t3;
                *reinterpret_cast<float4*>(Cf + gb + (j << 2)) = o;
            }
        }
    }
}

// ---------------------------------------------------------------------------
// Tensor-core assignment: 128 tokens/block vs all 512 centroids.
// Same fp16x3 machinery; flattened (ct,chunk) pipeline: 4 ct-tiles x 8 chunks.
// score = c2[k] + e2[i] - 2*dot; per-thread running (min, first-index),
// then 16-slot smem reduction (round-3 pattern).
// ---------------------------------------------------------------------------
#define ASSIGN_SMEM 81920

__global__ __launch_bounds__(256)
void assign_mma(const half* __restrict__ Sh, const half* __restrict__ Sl,
                int modal)
{
    extern __shared__ __align__(16) char smem[];
    const uint32_t sb0 = smem_u32(smem);
    const int tid  = threadIdx.x;
    const int lane = tid & 31, wid = tid >> 5;
    const int warpRow = wid >> 2, warpCol = wid & 3;
    const int g = lane >> 2, tig = lane & 3;
    const int rowBase = blockIdx.x << 7;

    const int fr = tid >> 1, fb = (tid & 1) << 1;
    const half* pAh = Sh + (size_t)(rowBase + fr) * SEND + fb * 8;
    const half* pAl = Sl + (size_t)(rowBase + fr) * SEND + fb * 8;
    const uint32_t dAB = sb0 + fr * 80 + fb * 16;

    const uint32_t loff = (uint32_t)(((lane & 7) + ((lane >> 3) & 1) * 8) * 80
                                     + ((lane >> 4) & 1) * 16);

    float e2r[8];
#pragma unroll
    for (int mt = 0; mt < 4; ++mt)
#pragma unroll
        for (int h = 0; h < 2; ++h)
            e2r[mt * 2 + h] =
                g_e2[modal * NTOK + rowBase + warpRow * 64 + mt * 16 + g + h * 8];

    float bestV[8]; int bestI[8];
#pragma unroll
    for (int i = 0; i < 8; ++i) { bestV[i] = 3.4e38f; bestI[i] = 0; }

    float acc[64];
#pragma unroll
    for (int i = 0; i < 64; ++i) acc[i] = 0.0f;

    auto ISSUE = [&](int t) {
        const int ct = t >> 3, c = t & 7;
        const int kh = c << 5;
        uint32_t d = dAB + (uint32_t)(t & 1) * STAGE_B;
        CPA16(d,              pAh + kh); CPA16(d + 16,              pAh + kh + 8);
        CPA16(d + TILE_B,     pAl + kh); CPA16(d + TILE_B + 16,     pAl + kh + 8);
        const half* pBh = g_ch + (size_t)(ct * 128 + fr) * SEND + fb * 8 + kh;
        const half* pBl = g_cl + (size_t)(ct * 128 + fr) * SEND + fb * 8 + kh;
        CPA16(d + 2 * TILE_B, pBh);      CPA16(d + 2 * TILE_B + 16, pBh + 8);
        CPA16(d + 3 * TILE_B, pBl);      CPA16(d + 3 * TILE_B + 16, pBl + 8);
    };

    auto COMPUTE = [&](int s) {
        const uint32_t base  = sb0 + s * STAGE_B;
        const uint32_t aBase = base + (warpRow * 64) * 80 + loff;
        const uint32_t bBase = base + 2 * TILE_B + (warpCol * 32) * 80 + loff;
#pragma unroll
        for (int ks = 0; ks < 2; ++ks) {
            const uint32_t kof = ks << 5;
            uint32_t ah[4][4], al[4][4], bh[4][2], bl[4][2];
#pragma unroll
            for (int mt = 0; mt < 4; ++mt) {
                uint32_t ad = aBase + mt * (16 * 80) + kof;
                LDMX4(ah[mt][0], ah[mt][1], ah[mt][2], ah[mt][3], ad);
                LDMX4(al[mt][0], al[mt][1], al[mt][2], al[mt][3], ad + TILE_B);
            }
#pragma unroll
            for (int p = 0; p < 2; ++p) {
                uint32_t bd = bBase + p * (16 * 80) + kof;
                uint32_t r0, r1, r2, r3;
                LDMX4(r0, r1, r2, r3, bd);
                bh[2 * p][0] = r0; bh[2 * p + 1][0] = r1;
                bh[2 * p][1] = r2; bh[2 * p + 1][1] = r3;
                LDMX4(r0, r1, r2, r3, bd + TILE_B);
                bl[2 * p][0] = r0; bl[2 * p + 1][0] = r1;
                bl[2 * p][1] = r2; bl[2 * p + 1][1] = r3;
            }
#pragma unroll
            for (int mt = 0; mt < 4; ++mt)
#pragma unroll
                for (int nt = 0; nt < 4; ++nt)
                    MMA16816(&acc[(mt * 4 + nt) * 4], ah[mt], bh[nt]);
#pragma unroll
            for (int mt = 0; mt < 4; ++mt)
#pragma unroll
                for (int nt = 0; nt < 4; ++nt)
                    MMA16816(&acc[(mt * 4 + nt) * 4], ah[mt], bl[nt]);
#pragma unroll
            for (int mt = 0; mt < 4; ++mt)
#pragma unroll
                for (int nt = 0; nt < 4; ++nt)
                    MMA16816(&acc[(mt * 4 + nt) * 4], al[mt], bh[nt]);
        }
    };

    ISSUE(0);
    CPA_COMMIT();
    for (int t = 0; t < 32; ++t) {
        if (t + 1 < 32) {
            ISSUE(t + 1);
            CPA_COMMIT();
            CPA_WAIT1();
        } else {
            CPA_WAIT0();
        }
        __syncthreads();
        COMPUTE(t & 1);
        __syncthreads();

        if ((t & 7) == 7) {               // finished one 128-centroid tile
            const int ct = t >> 3;
#pragma unroll
            for (int nt = 0; nt < 4; ++nt)
#pragma unroll
                for (int j = 0; j < 2; ++j) {
                    int col = ct * 128 + warpCol * 32 + nt * 8 + tig * 2 + j;
                    float c2v = g_c2[col];
#pragma unroll
                    for (int mt = 0; mt < 4; ++mt)
#pragma unroll
                        for (int h = 0; h < 2; ++h) {
                            float s = (c2v + e2r[mt * 2 + h]) -
                                2.0f * (acc[(mt * 4 + nt) * 4 + h * 2 + j] * OSCALE);
                            int bi = mt * 2 + h;
                            if (s < bestV[bi] ||
                                (s == bestV[bi] && col < bestI[bi])) {
                                bestV[bi] = s; bestI[bi] = col;
                            }
                        }
                }
#pragma unroll
            for (int i = 0; i < 64; ++i) acc[i] = 0.0f;
        }
    }

    // ---- cross-thread reduction (16 slots per row)
    float (*rv)[16] = reinterpret_cast<float(*)[16]>(smem);
    int   (*ri)[16] = reinterpret_cast<int(*)[16]>(smem + 8192);
    const int slot = warpCol * 4 + tig;
#pragma unroll
    for (int mt = 0; mt < 4; ++mt)
#pragma unroll
        for (int h = 0; h < 2; ++h) {
            int row = warpRow * 64 + mt * 16 + g + h * 8;
            rv[row][slot] = bestV[mt * 2 + h];
            ri[row][slot] = bestI[mt * 2 + h];
        }
    __syncthreads();
    if (tid < 128) {
        float bv = rv[tid][0]; int bi = ri[tid][0];
#pragma unroll
        for (int u = 1; u < 16; ++u) {
            float v = rv[tid][u]; int ix = ri[tid][u];
            if (v < bv || (v == bv && ix < bi)) { bv = v; bi = ix; }
        }
        g_sc[modal * NTOK + rowBase + tid] = bi;
    }
}

// ---------------------------------------------------------------------------
// emb fp32 -> (hi, lo) halves, scaled
// ---------------------------------------------------------------------------
__global__ void split_src(const float* __restrict__ X,
                          half* __restrict__ Xh, half* __restrict__ Xl)
{
    int i = blockIdx.x * blockDim.x + threadIdx.x;
    float4 v = reinterpret_cast<const float4*>(X)[i];
    half h0, h1, h2, h3, l0, l1, l2, l3;
    split2(v.x * SCALE_A, h0, l0); split2(v.y * SCALE_A, h1, l1);
    split2(v.z * SCALE_A, h2, l2); split2(v.w * SCALE_A, h3, l3);
    half2 ph0 = __halves2half2(h0, h1), ph1 = __halves2half2(h2, h3);
    half2 pl0 = __halves2half2(l0, l1), pl1 = __halves2half2(l2, l3);
    uint2 uh, ul;
    uh.x = reinterpret_cast<uint32_t&>(ph0); uh.y = reinterpret_cast<uint32_t&>(ph1);
    ul.x = reinterpret_cast<uint32_t&>(pl0); ul.y = reinterpret_cast<uint32_t&>(pl1);
    reinterpret_cast<uint2*>(Xh)[i] = uh;
    reinterpret_cast<uint2*>(Xl)[i] = ul;
}

// W[K,N] fp32 -> Th/Tl[N,K] halves, scaled
__global__ void transpose_split(const float* __restrict__ W,
                                half* __restrict__ Th, half* __restrict__ Tl,
                                int K, int N)
{
    __shared__ float t[32][33];
    const int bx = blockIdx.x << 5;
    const int by = blockIdx.y << 5;
#pragma unroll
    for (int j = 0; j < 32; j += 8)
        t[threadIdx.y + j][threadIdx.x] =
            W[(size_t)(by + threadIdx.y + j) * N + bx + threadIdx.x];
    __syncthreads();
#pragma unroll
    for (int j = 0; j < 32; j += 8) {
        float f = t[threadIdx.x][threadIdx.y + j] * SCALE_B;
        half h, l;
        split2(f, h, l);
        size_t o = (size_t)(bx + threadIdx.y + j) * K + by + threadIdx.x;
        Th[o] = h;
        Tl[o] = l;
    }
}

// ---------------------------------------------------------------------------
// centroids = tanh(raw) -> d_out, plus scaled split halves for assign_mma
// ---------------------------------------------------------------------------
__global__ void centroid_tanh(const float* __restrict__ raw, float* __restrict__ out)
{
    int i = blockIdx.x * blockDim.x + threadIdx.x;
    float t = tanhf(raw[i]);
    out[CENT_OFF + i] = t;
    half h, l;
    split2(t * SCALE_B, h, l);
    g_ch[i] = h;
    g_cl[i] = l;
}

__global__ void c2_kernel(const float* __restrict__ cent)
{
    int w    = (blockIdx.x * blockDim.x + threadIdx.x) >> 5;
    int lane = threadIdx.x & 31;
    if (w >= KC) return;
    const float* row = cent + (size_t)w * SEND;
    float s = 0.0f;
#pragma unroll
    for (int j = 0; j < 8; ++j) { float v = row[lane + j * 32]; s = fmaf(v, v, s); }
#pragma unroll
    for (int o = 16; o > 0; o >>= 1) s += __shfl_xor_sync(0xffffffffu, s, o);
    if (lane == 0) g_c2[w] = s;
}

__global__ void e2_kernel(const float* __restrict__ SE, int modal)
{
    int w    = (blockIdx.x * blockDim.x + threadIdx.x) >> 5;
    int lane = threadIdx.x & 31;
    const float* row = SE + (size_t)w * SEND;
    float s = 0.0f;
#pragma unroll
    for (int j = 0; j < 8; ++j) { float v = row[lane + j * 32]; s = fmaf(v, v, s); }
#pragma unroll
    for (int o = 16; o > 0; o >>= 1) s += __shfl_xor_sync(0xffffffffu, s, o);
    if (lane == 0) g_e2[modal * NTOK + w] = s;
}

// ---------------------------------------------------------------------------
// Counting sort (stable)
// ---------------------------------------------------------------------------
__global__ void zero_counts()
{
    int i = blockIdx.x * blockDim.x + threadIdx.x;
    if (i < 2 * KC) g_counts[i] = 0;
}

__global__ void count_kernel(int modal)
{
    int i = blockIdx.x * blockDim.x + threadIdx.x;
    atomicAdd(&g_counts[modal * KC + g_sc[modal * NTOK + i]], 1);
}

__global__ void scan_kernel(int modal)
{
    __shared__ int tmp[KC];
    int t = threadIdx.x;
    int v = g_counts[modal * KC + t];
    tmp[t] = v;
    __syncthreads();
    for (int off = 1; off < KC; off <<= 1) {
        int x = (t >= off) ? tmp[t - off] : 0;
        __syncthreads();
        tmp[t] += x;
        __syncthreads();
    }
    g_offsets[modal * KC + t] = tmp[t] - v;
}

__global__ void scatter_kernel(int modal, float* __restrict__ order)
{
    const int k = blockIdx.x;
    const int base0 = modal * NTOK;
    __shared__ int warpTot[8];
    int base = g_offsets[modal * KC + k];
    int lane = threadIdx.x & 31, wid = threadIdx.x >> 5;

    for (int start = 0; start < NTOK; start += 256) {
        int i = start + threadIdx.x;
        bool m = (g_sc[base0 + i] == k);
        unsigned b = __ballot_sync(0xffffffffu, m);
        if (lane == 0) warpTot[wid] = __popc(b);
        __syncthreads();
        int woff = 0, tot = 0;
#pragma unroll
        for (int w = 0; w < 8; ++w) { int c = warpTot[w]; tot += c; if (w < wid) woff += c; }
        if (m) order[base + woff + __popc(b & ((1u << lane) - 1u))] = (float)i;
        base += tot;
        __syncthreads();
    }
}

// ---------------------------------------------------------------------------
// word_class / sense_class / counts
// ---------------------------------------------------------------------------
__global__ void finalize_kernel(float* __restrict__ out)
{
    int i = blockIdx.x * blockDim.x + threadIdx.x;
    out[WC_OFF + i]  = (i < NTOK) ? 0.0f : 1.0f;
    out[SCL_OFF + i] = (float)g_sc[i];
}

__global__ void counts_out_kernel(float* __restrict__ out)
{
    int i = blockIdx.x * blockDim.x + threadIdx.x;
    if (i < 2 * KC) {
        int m = i >> 9, k = i & 511;
        out[(m ? CI_OFF : CT_OFF) + k] = (float)g_counts[i];
    }
}

// ---------------------------------------------------------------------------
// Launch
// ---------------------------------------------------------------------------
extern "C" void kernel_launch(void* const* d_in, const int* in_sizes, int n_in,
                              void* d_out, int out_size)
{
    const float* emb[2] = { (const float*)d_in[0], (const float*)d_in[1] };
    const float* W1[2]  = { (const float*)d_in[2], (const float*)d_in[5] };
    const float* W2[2]  = { (const float*)d_in[3], (const float*)d_in[6] };
    const float* W3[2]  = { (const float*)d_in[4], (const float*)d_in[7] };
    const float* craw   = (const float*)d_in[8];
    float* out = (float*)d_out;

    half *xh1, *xl1, *xh2, *xl2, *wh, *wl;
    cudaGetSymbolAddress((void**)&xh1, g_xh1);
    cudaGetSymbolAddress((void**)&xl1, g_xl1);
    cudaGetSymbolAddress((void**)&xh2, g_xh2);
    cudaGetSymbolAddress((void**)&xl2, g_xl2);
    cudaGetSymbolAddress((void**)&wh, g_wh);
    cudaGetSymbolAddress((void**)&wl, g_wl);

    cudaFuncSetAttribute(gemm_split<1>,
                         cudaFuncAttributeMaxDynamicSharedMemorySize, GEMM_SMEM);
    cudaFuncSetAttribute(gemm_split<2>,
                         cudaFuncAttributeMaxDynamicSharedMemorySize, GEMM_SMEM);
    cudaFuncSetAttribute(assign_mma,
                         cudaFuncAttributeMaxDynamicSharedMemorySize, ASSIGN_SMEM);

    centroid_tanh<<<(KC * SEND) / 256, 256>>>(craw, out);
    c2_kernel<<<(KC * 32) / 256, 256>>>(out + CENT_OFF);
    zero_counts<<<4, 256>>>();

    for (int m = 0; m < 2; ++m) {
        float* se = out + SE_OFF + (size_t)m * NTOK * SEND;

        split_src<<<(NTOK * TOKD / 4) / 256, 256>>>(emb[m], xh1, xl1);

        transpose_split<<<dim3(HIDD / 32, TOKD / 32), dim3(32, 8)>>>(W1[m], wh, wl, TOKD, HIDD);
        gemm_split<1><<<dim3(HIDD / 128, NTOK / 128), 256, GEMM_SMEM>>>(
            xh1, xl1, wh, wl, nullptr, xh2, xl2, TOKD, HIDD);

        transpose_split<<<dim3(HIDD / 32, HIDD / 32), dim3(32, 8)>>>(W2[m], wh, wl, HIDD, HIDD);
        gemm_split<1><<<dim3(HIDD / 128, NTOK / 128), 256, GEMM_SMEM>>>(
            xh2, xl2, wh, wl, nullptr, xh1, xl1, HIDD, HIDD);

        transpose_split<<<dim3(SEND / 32, HIDD / 32), dim3(32, 8)>>>(W3[m], wh, wl, HIDD, SEND);
        gemm_split<2><<<dim3(SEND / 128, NTOK / 128), 256, GEMM_SMEM>>>(
            xh1, xl1, wh, wl, se, xh2, xl2, HIDD, SEND);

        e2_kernel<<<(NTOK * 32) / 256, 256>>>(se, m);
        assign_mma<<<NTOK / 128, 256, ASSIGN_SMEM>>>(xh2, xl2, m);

        count_kernel<<<NTOK / 256, 256>>>(m);
        scan_kernel<<<1, KC>>>(m);
        scatter_kernel<<<KC, 256>>>(m, out + (m ? OI_OFF : OT_OFF));
    }

    finalize_kernel<<<(2 * NTOK) / 256, 256>>>(out);
    counts_out_kernel<<<4, 256>>>(out);
}

// round 12
// speedup vs baseline: 1.9679x; 1.0065x over previous
#include <cuda_runtime.h>
#include <cuda_fp16.h>
#include <math.h>
#include <stdint.h>

// ---------------------------------------------------------------------------
// Problem constants
// ---------------------------------------------------------------------------
#define NTOK 32768
#define TOKD 1024
#define HIDD 1024
#define SEND 256
#define KC   512

// d_out float offsets (flattened reference tuple, fp32)
#define CENT_OFF 0
#define SE_OFF   131072
#define WC_OFF   16908288
#define SCL_OFF  16973824
#define OT_OFF   17039360
#define CT_OFF   17072128
#define OI_OFF   17072640
#define CI_OFF   17105408

#define SCALE_A 16.0f
#define SCALE_B 64.0f
#define OSCALE  (1.0f / 1024.0f)

// ---------------------------------------------------------------------------
// Scratch (device globals)
// ---------------------------------------------------------------------------
__device__ half  g_xh1[(size_t)NTOK * HIDD];
__device__ half  g_xl1[(size_t)NTOK * HIDD];
__device__ half  g_xh2[(size_t)NTOK * HIDD];
__device__ half  g_xl2[(size_t)NTOK * HIDD];
__device__ half  g_w1h[2][(size_t)HIDD * HIDD];   // transposed weights, N-major
__device__ half  g_w1l[2][(size_t)HIDD * HIDD];
__device__ half  g_w2h[2][(size_t)HIDD * HIDD];
__device__ half  g_w2l[2][(size_t)HIDD * HIDD];
__device__ half  g_w3h[2][(size_t)SEND * HIDD];
__device__ half  g_w3l[2][(size_t)SEND * HIDD];
__device__ half  g_ch[(size_t)KC * SEND];         // centroids hi (x64)
__device__ half  g_cl[(size_t)KC * SEND];         // centroids lo
__device__ float g_c2[KC];
__device__ float g_e2p[4 * NTOK];                 // [plane(2)][modal(2)][NTOK]
__device__ int   g_sc[2 * NTOK];
__device__ int   g_counts[2 * KC];
__device__ int   g_offsets[2 * KC];

// ---------------------------------------------------------------------------
// PTX helpers (sm_80-era, portable under compute_100)
// ---------------------------------------------------------------------------
__device__ __forceinline__ uint32_t smem_u32(const void* p) {
    uint32_t a;
    asm("{ .reg .u64 t; cvta.to.shared.u64 t, %1; cvt.u32.u64 %0, t; }"
        : "=r"(a) : "l"(p));
    return a;
}

#define MMA16816(d, a, b) \
    asm volatile( \
        "mma.sync.aligned.m16n8k16.row.col.f32.f16.f16.f32 " \
        "{%0,%1,%2,%3}, {%4,%5,%6,%7}, {%8,%9}, {%0,%1,%2,%3};" \
        : "+f"((d)[0]), "+f"((d)[1]), "+f"((d)[2]), "+f"((d)[3]) \
        : "r"((a)[0]), "r"((a)[1]), "r"((a)[2]), "r"((a)[3]), \
          "r"((b)[0]), "r"((b)[1]))

#define LDMX4(r0, r1, r2, r3, addr) \
    asm volatile("ldmatrix.sync.aligned.m8n8.x4.shared.b16 {%0,%1,%2,%3}, [%4];" \
        : "=r"(r0), "=r"(r1), "=r"(r2), "=r"(r3) : "r"(addr))

#define CPA16(dst, src) \
    asm volatile("cp.async.ca.shared.global [%0], [%1], 16;" :: "r"(dst), "l"(src))
#define CPA_COMMIT() asm volatile("cp.async.commit_group;")
#define CPA_WAIT1()  asm volatile("cp.async.wait_group 1;")
#define CPA_WAIT0()  asm volatile("cp.async.wait_group 0;")

__device__ __forceinline__ void split2(float f, half& h, half& l) {
    h = __float2half_rn(f);
    l = __float2half_rn(f - __half2float(h));
}

// ---------------------------------------------------------------------------
// fp16x3 split-GEMM (proven round-7/11 kernel).
// OMODE: 1 = split (hi,lo)*SCALE_A out; 2 = fp32 out + split out + e2 partials.
// ---------------------------------------------------------------------------
#define TILE_B    10240         // 128 rows * 80 B
#define STAGE_B   40960         // Ah | Al | Bh | Bl tiles
#define GEMM_SMEM 81920         // 2 stages

template<int OMODE>
__global__ __launch_bounds__(256)
void gemm_split(const half* __restrict__ Ah, const half* __restrict__ Al,
                const half* __restrict__ Bh, const half* __restrict__ Bl,
                float* __restrict__ Cf,
                half* __restrict__ Coh, half* __restrict__ Col,
                float* __restrict__ E2p,       // base + modal*NTOK (OMODE==2)
                int Kdim, int Mcols)
{
    extern __shared__ __align__(16) char smem[];
    const uint32_t sb0 = smem_u32(smem);

    const int tid  = threadIdx.x;
    const int lane = tid & 31, wid = tid >> 5;
    const int warpRow = wid >> 2;
    const int warpCol = wid & 3;
    const int g = lane >> 2, tig = lane & 3;
    const int blockRow = blockIdx.y << 7;
    const int blockCol = blockIdx.x << 7;

    float acc[64];
#pragma unroll
    for (int i = 0; i < 64; ++i) acc[i] = 0.0f;

    const int fr = tid >> 1;
    const int fb = (tid & 1) << 1;
    const half* srcA  = Ah + (size_t)(blockRow + fr) * Kdim + fb * 8;
    const half* srcAl = Al + (size_t)(blockRow + fr) * Kdim + fb * 8;
    const half* srcB  = Bh + (size_t)(blockCol + fr) * Kdim + fb * 8;
    const half* srcBl = Bl + (size_t)(blockCol + fr) * Kdim + fb * 8;
    const uint32_t dstBase = sb0 + fr * 80 + fb * 16;

    const uint32_t loff = (uint32_t)(((lane & 7) + ((lane >> 3) & 1) * 8) * 80
                                     + ((lane >> 4) & 1) * 16);

    const int chunks = Kdim >> 5;

    auto ISSUE = [&](int c) {
        const int s = c & 1;
        const int kh = c << 5;
        uint32_t d = dstBase + s * STAGE_B;
        CPA16(d,              srcA + kh);  CPA16(d + 16,              srcA + kh + 8);
        CPA16(d + TILE_B,     srcAl + kh); CPA16(d + TILE_B + 16,     srcAl + kh + 8);
        CPA16(d + 2 * TILE_B, srcB + kh);  CPA16(d + 2 * TILE_B + 16, srcB + kh + 8);
        CPA16(d + 3 * TILE_B, srcBl + kh); CPA16(d + 3 * TILE_B + 16, srcBl + kh + 8);
    };

    auto COMPUTE = [&](int s) {
        const uint32_t base  = sb0 + s * STAGE_B;
        const uint32_t aBase = base + (warpRow * 64) * 80 + loff;
        const uint32_t bBase = base + 2 * TILE_B + (warpCol * 32) * 80 + loff;
#pragma unroll
        for (int ks = 0; ks < 2; ++ks) {
            const uint32_t kof = ks << 5;
            uint32_t ah[4][4], al[4][4], bh[4][2], bl[4][2];
#pragma unroll
            for (int mt = 0; mt < 4; ++mt) {
                uint32_t ad = aBase + mt * (16 * 80) + kof;
                LDMX4(ah[mt][0], ah[mt][1], ah[mt][2], ah[mt][3], ad);
                LDMX4(al[mt][0], al[mt][1], al[mt][2], al[mt][3], ad + TILE_B);
            }
#pragma unroll
            for (int p = 0; p < 2; ++p) {
                uint32_t bd = bBase + p * (16 * 80) + kof;
                uint32_t r0, r1, r2, r3;
                LDMX4(r0, r1, r2, r3, bd);
                bh[2 * p][0] = r0; bh[2 * p + 1][0] = r1;
                bh[2 * p][1] = r2; bh[2 * p + 1][1] = r3;
                LDMX4(r0, r1, r2, r3, bd + TILE_B);
                bl[2 * p][0] = r0; bl[2 * p + 1][0] = r1;
                bl[2 * p][1] = r2; bl[2 * p + 1][1] = r3;
            }
#pragma unroll
            for (int mt = 0; mt < 4; ++mt)
#pragma unroll
                for (int nt = 0; nt < 4; ++nt)
                    MMA16816(&acc[(mt * 4 + nt) * 4], ah[mt], bh[nt]);
#pragma unroll
            for (int mt = 0; mt < 4; ++mt)
#pragma unroll
                for (int nt = 0; nt < 4; ++nt)
                    MMA16816(&acc[(mt * 4 + nt) * 4], ah[mt], bl[nt]);
#pragma unroll
            for (int mt = 0; mt < 4; ++mt)
#pragma unroll
                for (int nt = 0; nt < 4; ++nt)
                    MMA16816(&acc[(mt * 4 + nt) * 4], al[mt], bh[nt]);
        }
    };

    ISSUE(0);
    CPA_COMMIT();
    for (int c = 0; c < chunks; ++c) {
        if (c + 1 < chunks) {
            ISSUE(c + 1);
            CPA_COMMIT();
            CPA_WAIT1();
        } else {
            CPA_WAIT0();
        }
        __syncthreads();
        COMPUTE(c & 1);
        __syncthreads();
    }

    // ---- epilogue: stage fp32 acc in smem, then coalesced transform+store
    float* cst = reinterpret_cast<float*>(smem);   // [128][132]
#pragma unroll
    for (int mt = 0; mt < 4; ++mt)
#pragma unroll
        for (int nt = 0; nt < 4; ++nt) {
            const float* a4 = &acc[(mt * 4 + nt) * 4];
            int r0 = (warpRow << 6) + (mt << 4) + g;
            int cc = (warpCol << 5) + (nt << 3) + (tig << 1);
            *reinterpret_cast<float2*>(cst + r0 * 132 + cc) =
                make_float2(a4[0], a4[1]);
            *reinterpret_cast<float2*>(cst + (r0 + 8) * 132 + cc) =
                make_float2(a4[2], a4[3]);
        }
    __syncthreads();
    {
        const int row  = tid >> 1;
        const int colh = (tid & 1) << 6;
        const float* src = cst + row * 132 + colh;
        const size_t gb = (size_t)(blockRow + row) * Mcols + blockCol + colh;
        float ss = 0.0f;
#pragma unroll
        for (int j = 0; j < 16; ++j) {
            float4 v = *reinterpret_cast<const float4*>(src + (j << 2));
            float t0 = tanhf(v.x * OSCALE), t1 = tanhf(v.y * OSCALE);
            float t2 = tanhf(v.z * OSCALE), t3 = tanhf(v.w * OSCALE);
            if (OMODE >= 1) {
                half h0, h1, h2, h3, l0, l1, l2, l3;
                split2(t0 * SCALE_A, h0, l0); split2(t1 * SCALE_A, h1, l1);
                split2(t2 * SCALE_A, h2, l2); split2(t3 * SCALE_A, h3, l3);
                half2 ph0 = __halves2half2(h0, h1), ph1 = __halves2half2(h2, h3);
                half2 pl0 = __halves2half2(l0, l1), pl1 = __halves2half2(l2, l3);
                uint2 uh, ul;
                uh.x = reinterpret_cast<uint32_t&>(ph0);
                uh.y = reinterpret_cast<uint32_t&>(ph1);
                ul.x = reinterpret_cast<uint32_t&>(pl0);
                ul.y = reinterpret_cast<uint32_t&>(pl1);
                *reinterpret_cast<uint2*>(Coh + gb + (j << 2)) = uh;
                *reinterpret_cast<uint2*>(Col + gb + (j << 2)) = ul;
            }
            if (OMODE == 2) {
                ss = fmaf(t0, t0, ss); ss = fmaf(t1, t1, ss);
                ss = fmaf(t2, t2, ss); ss = fmaf(t3, t3, ss);
                float4 o; o.x = t0; o.y = t1; o.z = t2; o.w = t3;
                *reinterpret_cast<float4*>(Cf + gb + (j << 2)) = o;
            }
        }
        // e2 partial per column-block plane (deterministic smem combine)
        if (OMODE == 2) {
            float* e2s = reinterpret_cast<float*>(smem) + 16896;   // past cst
            e2s[tid] = ss;                       // index = row*2 + half
            __syncthreads();
            if ((tid & 1) == 0)
                E2p[(size_t)blockIdx.x * (2 * NTOK) + blockRow + (tid >> 1)] =
                    e2s[tid] + e2s[tid + 1];
        }
    }
}

// ---------------------------------------------------------------------------
// Tensor-core assignment (round-11 proven) + fused count.
// ---------------------------------------------------------------------------
#define ASSIGN_SMEM 81920

__global__ __launch_bounds__(256)
void assign_mma(const half* __restrict__ Sh, const half* __restrict__ Sl,
                int modal)
{
    extern __shared__ __align__(16) char smem[];
    const uint32_t sb0 = smem_u32(smem);
    const int tid  = threadIdx.x;
    const int lane = tid & 31, wid = tid >> 5;
    const int warpRow = wid >> 2, warpCol = wid & 3;
    const int g = lane >> 2, tig = lane & 3;
    const int rowBase = blockIdx.x << 7;

    const int fr = tid >> 1, fb = (tid & 1) << 1;
    const half* pAh = Sh + (size_t)(rowBase + fr) * SEND + fb * 8;
    const half* pAl = Sl + (size_t)(rowBase + fr) * SEND + fb * 8;
    const uint32_t dAB = sb0 + fr * 80 + fb * 16;

    const uint32_t loff = (uint32_t)(((lane & 7) + ((lane >> 3) & 1) * 8) * 80
                                     + ((lane >> 4) & 1) * 16);

    float e2r[8];
#pragma unroll
    for (int mt = 0; mt < 4; ++mt)
#pragma unroll
        for (int h = 0; h < 2; ++h) {
            int idx = modal * NTOK + rowBase + warpRow * 64 + mt * 16 + g + h * 8;
            e2r[mt * 2 + h] = g_e2p[idx] + g_e2p[2 * NTOK + idx];
        }

    float bestV[8]; int bestI[8];
#pragma unroll
    for (int i = 0; i < 8; ++i) { bestV[i] = 3.4e38f; bestI[i] = 0; }

    float acc[64];
#pragma unroll
    for (int i = 0; i < 64; ++i) acc[i] = 0.0f;

    auto ISSUE = [&](int t) {
        const int ct = t >> 3, c = t & 7;
        const int kh = c << 5;
        uint32_t d = dAB + (uint32_t)(t & 1) * STAGE_B;
        CPA16(d,              pAh + kh); CPA16(d + 16,              pAh + kh + 8);
        CPA16(d + TILE_B,     pAl + kh); CPA16(d + TILE_B + 16,     pAl + kh + 8);
        const half* pBh = g_ch + (size_t)(ct * 128 + fr) * SEND + fb * 8 + kh;
        const half* pBl = g_cl + (size_t)(ct * 128 + fr) * SEND + fb * 8 + kh;
        CPA16(d + 2 * TILE_B, pBh);      CPA16(d + 2 * TILE_B + 16, pBh + 8);
        CPA16(d + 3 * TILE_B, pBl);      CPA16(d + 3 * TILE_B + 16, pBl + 8);
    };

    auto COMPUTE = [&](int s) {
        const uint32_t base  = sb0 + s * STAGE_B;
        const uint32_t aBase = base + (warpRow * 64) * 80 + loff;
        const uint32_t bBase = base + 2 * TILE_B + (warpCol * 32) * 80 + loff;
#pragma unroll
        for (int ks = 0; ks < 2; ++ks) {
            const uint32_t kof = ks << 5;
            uint32_t ah[4][4], al[4][4], bh[4][2], bl[4][2];
#pragma unroll
            for (int mt = 0; mt < 4; ++mt) {
                uint32_t ad = aBase + mt * (16 * 80) + kof;
                LDMX4(ah[mt][0], ah[mt][1], ah[mt][2], ah[mt][3], ad);
                LDMX4(al[mt][0], al[mt][1], al[mt][2], al[mt][3], ad + TILE_B);
            }
#pragma unroll
            for (int p = 0; p < 2; ++p) {
                uint32_t bd = bBase + p * (16 * 80) + kof;
                uint32_t r0, r1, r2, r3;
                LDMX4(r0, r1, r2, r3, bd);
                bh[2 * p][0] = r0; bh[2 * p + 1][0] = r1;
                bh[2 * p][1] = r2; bh[2 * p + 1][1] = r3;
                LDMX4(r0, r1, r2, r3, bd + TILE_B);
                bl[2 * p][0] = r0; bl[2 * p + 1][0] = r1;
                bl[2 * p][1] = r2; bl[2 * p + 1][1] = r3;
            }
#pragma unroll
            for (int mt = 0; mt < 4; ++mt)
#pragma unroll
                for (int nt = 0; nt < 4; ++nt)
                    MMA16816(&acc[(mt * 4 + nt) * 4], ah[mt], bh[nt]);
#pragma unroll
            for (int mt = 0; mt < 4; ++mt)
#pragma unroll
                for (int nt = 0; nt < 4; ++nt)
                    MMA16816(&acc[(mt * 4 + nt) * 4], ah[mt], bl[nt]);
#pragma unroll
            for (int mt = 0; mt < 4; ++mt)
#pragma unroll
                for (int nt = 0; nt < 4; ++nt)
                    MMA16816(&acc[(mt * 4 + nt) * 4], al[mt], bh[nt]);
        }
    };

    ISSUE(0);
    CPA_COMMIT();
    for (int t = 0; t < 32; ++t) {
        if (t + 1 < 32) {
            ISSUE(t + 1);
            CPA_COMMIT();
            CPA_WAIT1();
        } else {
            CPA_WAIT0();
        }
        __syncthreads();
        COMPUTE(t & 1);
        __syncthreads();

        if ((t & 7) == 7) {
            const int ct = t >> 3;
#pragma unroll
            for (int nt = 0; nt < 4; ++nt)
#pragma unroll
                for (int j = 0; j < 2; ++j) {
                    int col = ct * 128 + warpCol * 32 + nt * 8 + tig * 2 + j;
                    float c2v = g_c2[col];
#pragma unroll
                    for (int mt = 0; mt < 4; ++mt)
#pragma unroll
                        for (int h = 0; h < 2; ++h) {
                            float s = (c2v + e2r[mt * 2 + h]) -
                                2.0f * (acc[(mt * 4 + nt) * 4 + h * 2 + j] * OSCALE);
                            int bi = mt * 2 + h;
                            if (s < bestV[bi] ||
                                (s == bestV[bi] && col < bestI[bi])) {
                                bestV[bi] = s; bestI[bi] = col;
                            }
                        }
                }
#pragma unroll
            for (int i = 0; i < 64; ++i) acc[i] = 0.0f;
        }
    }

    // ---- cross-thread reduction (16 slots per row) + fused count
    float (*rv)[16] = reinterpret_cast<float(*)[16]>(smem);
    int   (*ri)[16] = reinterpret_cast<int(*)[16]>(smem + 8192);
    const int slot = warpCol * 4 + tig;
#pragma unroll
    for (int mt = 0; mt < 4; ++mt)
#pragma unroll
        for (int h = 0; h < 2; ++h) {
            int row = warpRow * 64 + mt * 16 + g + h * 8;
            rv[row][slot] = bestV[mt * 2 + h];
            ri[row][slot] = bestI[mt * 2 + h];
        }
    __syncthreads();
    if (tid < 128) {
        float bv = rv[tid][0]; int bi = ri[tid][0];
#pragma unroll
        for (int u = 1; u < 16; ++u) {
            float v = rv[tid][u]; int ix = ri[tid][u];
            if (v < bv || (v == bv && ix < bi)) { bv = v; bi = ix; }
        }
        g_sc[modal * NTOK + rowBase + tid] = bi;
        atomicAdd(&g_counts[modal * KC + bi], 1);
    }
}

// ---------------------------------------------------------------------------
// emb fp32 -> (hi, lo) halves, scaled
// ---------------------------------------------------------------------------
__global__ void split_src(const float* __restrict__ X,
                          half* __restrict__ Xh, half* __restrict__ Xl)
{
    int i = blockIdx.x * blockDim.x + threadIdx.x;
    float4 v = reinterpret_cast<const float4*>(X)[i];
    half h0, h1, h2, h3, l0, l1, l2, l3;
    split2(v.x * SCALE_A, h0, l0); split2(v.y * SCALE_A, h1, l1);
    split2(v.z * SCALE_A, h2, l2); split2(v.w * SCALE_A, h3, l3);
    half2 ph0 = __halves2half2(h0, h1), ph1 = __halves2half2(h2, h3);
    half2 pl0 = __halves2half2(l0, l1), pl1 = __halves2half2(l2, l3);
    uint2 uh, ul;
    uh.x = reinterpret_cast<uint32_t&>(ph0); uh.y = reinterpret_cast<uint32_t&>(ph1);
    ul.x = reinterpret_cast<uint32_t&>(pl0); ul.y = reinterpret_cast<uint32_t&>(pl1);
    reinterpret_cast<uint2*>(Xh)[i] = uh;
    reinterpret_cast<uint2*>(Xl)[i] = ul;
}

// ---------------------------------------------------------------------------
// All 6 weight transposes + splits in one launch.
// z = modal*3 + layer; W[K=1024, N] -> Th/Tl[N][1024], scaled by SCALE_B.
// ---------------------------------------------------------------------------
__global__ void transpose_split_all(
    const float* __restrict__ W10, const float* __restrict__ W20,
    const float* __restrict__ W30, const float* __restrict__ W11,
    const float* __restrict__ W21, const float* __restrict__ W31)
{
    const int z = blockIdx.z;
    const int m = z / 3, layer = z % 3;
    const int N = (layer == 2) ? SEND : HIDD;
    if ((blockIdx.x << 5) >= N) return;

    const float* W =
        (layer == 0) ? (m ? W11 : W10) :
        (layer == 1) ? (m ? W21 : W20) : (m ? W31 : W30);
    half* Th = (layer == 0) ? g_w1h[m] : (layer == 1) ? g_w2h[m] : g_w3h[m];
    half* Tl = (layer == 0) ? g_w1l[m] : (layer == 1) ? g_w2l[m] : g_w3l[m];

    __shared__ float t[32][33];
    const int bx = blockIdx.x << 5;   // n base
    const int by = blockIdx.y << 5;   // k base
#pragma unroll
    for (int j = 0; j < 32; j += 8)
        t[threadIdx.y + j][threadIdx.x] =
            W[(size_t)(by + threadIdx.y + j) * N + bx + threadIdx.x];
    __syncthreads();
#pragma unroll
    for (int j = 0; j < 32; j += 8) {
        float f = t[threadIdx.x][threadIdx.y + j] * SCALE_B;
        half h, l;
        split2(f, h, l);
        size_t o = (size_t)(bx + threadIdx.y + j) * HIDD + by + threadIdx.x;
        Th[o] = h;
        Tl[o] = l;
    }
}

// ---------------------------------------------------------------------------
// centroids = tanh(raw) -> d_out, plus scaled split halves for assign_mma
// ---------------------------------------------------------------------------
__global__ void centroid_tanh(const float* __restrict__ raw, float* __restrict__ out)
{
    int i = blockIdx.x * blockDim.x + threadIdx.x;
    float t = tanhf(raw[i]);
    out[CENT_OFF + i] = t;
    half h, l;
    split2(t * SCALE_B, h, l);
    g_ch[i] = h;
    g_cl[i] = l;
}

__global__ void c2_kernel(const float* __restrict__ cent)
{
    int w    = (blockIdx.x * blockDim.x + threadIdx.x) >> 5;
    int lane = threadIdx.x & 31;
    if (w >= KC) return;
    const float* row = cent + (size_t)w * SEND;
    float s = 0.0f;
#pragma unroll
    for (int j = 0; j < 8; ++j) { float v = row[lane + j * 32]; s = fmaf(v, v, s); }
#pragma unroll
    for (int o = 16; o > 0; o >>= 1) s += __shfl_xor_sync(0xffffffffu, s, o);
    if (lane == 0) g_c2[w] = s;
}

// ---------------------------------------------------------------------------
// Counting sort (stable)
// ---------------------------------------------------------------------------
__global__ void zero_counts()
{
    int i = blockIdx.x * blockDim.x + threadIdx.x;
    if (i < 2 * KC) g_counts[i] = 0;
}

__global__ void scan_kernel(int modal)
{
    __shared__ int tmp[KC];
    int t = threadIdx.x;
    int v = g_counts[modal * KC + t];
    tmp[t] = v;
    __syncthreads();
    for (int off = 1; off < KC; off <<= 1) {
        int x = (t >= off) ? tmp[t - off] : 0;
        __syncthreads();
        tmp[t] += x;
        __syncthreads();
    }
    g_offsets[modal * KC + t] = tmp[t] - v;
}

__global__ void scatter_kernel(int modal, float* __restrict__ order)
{
    const int k = blockIdx.x;
    const int base0 = modal * NTOK;
    __shared__ int warpTot[8];
    int base = g_offsets[modal * KC + k];
    int lane = threadIdx.x & 31, wid = threadIdx.x >> 5;

    for (int start = 0; start < NTOK; start += 256) {
        int i = start + threadIdx.x;
        bool m = (g_sc[base0 + i] == k);
        unsigned b = __ballot_sync(0xffffffffu, m);
        if (lane == 0) warpTot[wid] = __popc(b);
        __syncthreads();
        int woff = 0, tot = 0;
#pragma unroll
        for (int w = 0; w < 8; ++w) { int c = warpTot[w]; tot += c; if (w < wid) woff += c; }
        if (m) order[base + woff + __popc(b & ((1u << lane) - 1u))] = (float)i;
        base += tot;
        __syncthreads();
    }
}

// ---------------------------------------------------------------------------
// word_class / sense_class / counts
// ---------------------------------------------------------------------------
__global__ void finalize_kernel(float* __restrict__ out)
{
    int i = blockIdx.x * blockDim.x + threadIdx.x;
    out[WC_OFF + i]  = (i < NTOK) ? 0.0f : 1.0f;
    out[SCL_OFF + i] = (float)g_sc[i];
}

__global__ void counts_out_kernel(float* __restrict__ out)
{
    int i = blockIdx.x * blockDim.x + threadIdx.x;
    if (i < 2 * KC) {
        int m = i >> 9, k = i & 511;
        out[(m ? CI_OFF : CT_OFF) + k] = (float)g_counts[i];
    }
}

// ---------------------------------------------------------------------------
// Launch
// ---------------------------------------------------------------------------
extern "C" void kernel_launch(void* const* d_in, const int* in_sizes, int n_in,
                              void* d_out, int out_size)
{
    const float* emb[2] = { (const float*)d_in[0], (const float*)d_in[1] };
    const float* W1[2]  = { (const float*)d_in[2], (const float*)d_in[5] };
    const float* W2[2]  = { (const float*)d_in[3], (const float*)d_in[6] };
    const float* W3[2]  = { (const float*)d_in[4], (const float*)d_in[7] };
    const float* craw   = (const float*)d_in[8];
    float* out = (float*)d_out;

    half *xh1, *xl1, *xh2, *xl2;
    half *w1h, *w1l, *w2h, *w2l, *w3h, *w3l;
    float* e2p;
    cudaGetSymbolAddress((void**)&xh1, g_xh1);
    cudaGetSymbolAddress((void**)&xl1, g_xl1);
    cudaGetSymbolAddress((void**)&xh2, g_xh2);
    cudaGetSymbolAddress((void**)&xl2, g_xl2);
    cudaGetSymbolAddress((void**)&w1h, g_w1h);
    cudaGetSymbolAddress((void**)&w1l, g_w1l);
    cudaGetSymbolAddress((void**)&w2h, g_w2h);
    cudaGetSymbolAddress((void**)&w2l, g_w2l);
    cudaGetSymbolAddress((void**)&w3h, g_w3h);
    cudaGetSymbolAddress((void**)&w3l, g_w3l);
    cudaGetSymbolAddress((void**)&e2p, g_e2p);

    cudaFuncSetAttribute(gemm_split<1>,
                         cudaFuncAttributeMaxDynamicSharedMemorySize, GEMM_SMEM);
    cudaFuncSetAttribute(gemm_split<2>,
                         cudaFuncAttributeMaxDynamicSharedMemorySize, GEMM_SMEM);
    cudaFuncSetAttribute(assign_mma,
                         cudaFuncAttributeMaxDynamicSharedMemorySize, ASSIGN_SMEM);

    centroid_tanh<<<(KC * SEND) / 256, 256>>>(craw, out);
    c2_kernel<<<(KC * 32) / 256, 256>>>(out + CENT_OFF);
    zero_counts<<<4, 256>>>();
    transpose_split_all<<<dim3(32, 32, 6), dim3(32, 8)>>>(
        W1[0], W2[0], W3[0], W1[1], W2[1], W3[1]);

    const size_t WSZ = (size_t)HIDD * HIDD;
    const size_t W3SZ = (size_t)SEND * HIDD;

    for (int m = 0; m < 2; ++m) {
        float* se = out + SE_OFF + (size_t)m * NTOK * SEND;

        split_src<<<(NTOK * TOKD / 4) / 256, 256>>>(emb[m], xh1, xl1);

        gemm_split<1><<<dim3(HIDD / 128, NTOK / 128), 256, GEMM_SMEM>>>(
            xh1, xl1, w1h + m * WSZ, w1l + m * WSZ,
            nullptr, xh2, xl2, nullptr, TOKD, HIDD);

        gemm_split<1><<<dim3(HIDD / 128, NTOK / 128), 256, GEMM_SMEM>>>(
            xh2, xl2, w2h + m * WSZ, w2l + m * WSZ,
            nullptr, xh1, xl1, nullptr, HIDD, HIDD);

        gemm_split<2><<<dim3(SEND / 128, NTOK / 128), 256, GEMM_SMEM>>>(
            xh1, xl1, w3h + m * W3SZ, w3l + m * W3SZ,
            se, xh2, xl2, e2p + (size_t)m * NTOK, HIDD, SEND);

        assign_mma<<<NTOK / 128, 256, ASSIGN_SMEM>>>(xh2, xl2, m);

        scan_kernel<<<1, KC>>>(m);
        scatter_kernel<<<KC, 256>>>(m, out + (m ? OI_OFF : OT_OFF));
    }

    finalize_kernel<<<(2 * NTOK) / 256, 256>>>(out);
    counts_out_kernel<<<4, 256>>>(out);
}

// round 13
// speedup vs baseline: 1.9819x; 1.0071x over previous
#include <cuda_runtime.h>
#include <cuda_fp16.h>
#include <math.h>
#include <stdint.h>

// ---------------------------------------------------------------------------
// Problem constants
// ---------------------------------------------------------------------------
#define NTOK 32768
#define TOKD 1024
#define HIDD 1024
#define SEND 256
#define KC   512

// d_out float offsets (flattened reference tuple, fp32)
#define CENT_OFF 0
#define SE_OFF   131072
#define WC_OFF   16908288
#define SCL_OFF  16973824
#define OT_OFF   17039360
#define CT_OFF   17072128
#define OI_OFF   17072640
#define CI_OFF   17105408

#define SCALE_A 16.0f
#define SCALE_B 64.0f
#define OSCALE  (1.0f / 1024.0f)

// ---------------------------------------------------------------------------
// Scratch (device globals)
// ---------------------------------------------------------------------------
__device__ half  g_xh1[(size_t)NTOK * HIDD];
__device__ half  g_xl1[(size_t)NTOK * HIDD];
__device__ half  g_xh2[(size_t)NTOK * HIDD];
__device__ half  g_xl2[(size_t)NTOK * HIDD];
__device__ half  g_w1h[2][(size_t)HIDD * HIDD];   // transposed weights, N-major
__device__ half  g_w1l[2][(size_t)HIDD * HIDD];
__device__ half  g_w2h[2][(size_t)HIDD * HIDD];
__device__ half  g_w2l[2][(size_t)HIDD * HIDD];
__device__ half  g_w3h[2][(size_t)SEND * HIDD];
__device__ half  g_w3l[2][(size_t)SEND * HIDD];
__device__ half  g_ch[(size_t)KC * SEND];         // centroids hi (x64)
__device__ half  g_cl[(size_t)KC * SEND];         // centroids lo
__device__ float g_c2[KC];
__device__ float g_e2p[4 * NTOK];                 // [plane(2)][modal(2)][NTOK]
__device__ int   g_sc[2 * NTOK];
__device__ int   g_counts[2 * KC];
__device__ int   g_offsets[2 * KC];

// ---------------------------------------------------------------------------
// PTX helpers (sm_80-era, portable under compute_100)
// ---------------------------------------------------------------------------
__device__ __forceinline__ uint32_t smem_u32(const void* p) {
    uint32_t a;
    asm("{ .reg .u64 t; cvta.to.shared.u64 t, %1; cvt.u32.u64 %0, t; }"
        : "=r"(a) : "l"(p));
    return a;
}

#define MMA16816(d, a, b) \
    asm volatile( \
        "mma.sync.aligned.m16n8k16.row.col.f32.f16.f16.f32 " \
        "{%0,%1,%2,%3}, {%4,%5,%6,%7}, {%8,%9}, {%0,%1,%2,%3};" \
        : "+f"((d)[0]), "+f"((d)[1]), "+f"((d)[2]), "+f"((d)[3]) \
        : "r"((a)[0]), "r"((a)[1]), "r"((a)[2]), "r"((a)[3]), \
          "r"((b)[0]), "r"((b)[1]))

#define LDMX4(r0, r1, r2, r3, addr) \
    asm volatile("ldmatrix.sync.aligned.m8n8.x4.shared.b16 {%0,%1,%2,%3}, [%4];" \
        : "=r"(r0), "=r"(r1), "=r"(r2), "=r"(r3) : "r"(addr))

#define CPA16(dst, src) \
    asm volatile("cp.async.ca.shared.global [%0], [%1], 16;" :: "r"(dst), "l"(src))
#define CPA_COMMIT() asm volatile("cp.async.commit_group;")
#define CPA_WAIT0()  asm volatile("cp.async.wait_group 0;")

__device__ __forceinline__ void split2(float f, half& h, half& l) {
    h = __float2half_rn(f);
    l = __float2half_rn(f - __half2float(h));
}

// ---------------------------------------------------------------------------
// fp16x3 split-GEMM. Single-sync mainloop:
//   loop: WAIT0; sync (data visible + prev compute done); ISSUE(c+1); COMPUTE(c)
// cp.async of chunk c+1 overlaps COMPUTE(c) via the async engine.
// OMODE: 1 = split (hi,lo)*SCALE_A out; 2 = fp32 out + split out + e2 partials.
// ---------------------------------------------------------------------------
#define TILE_B    10240         // 128 rows * 80 B
#define STAGE_B   40960         // Ah | Al | Bh | Bl tiles
#define GEMM_SMEM 81920         // 2 stages

template<int OMODE>
__global__ __launch_bounds__(256)
void gemm_split(const half* __restrict__ Ah, const half* __restrict__ Al,
                const half* __restrict__ Bh, const half* __restrict__ Bl,
                float* __restrict__ Cf,
                half* __restrict__ Coh, half* __restrict__ Col,
                float* __restrict__ E2p,       // base + modal*NTOK (OMODE==2)
                int Kdim, int Mcols)
{
    extern __shared__ __align__(16) char smem[];
    const uint32_t sb0 = smem_u32(smem);

    const int tid  = threadIdx.x;
    const int lane = tid & 31, wid = tid >> 5;
    const int warpRow = wid >> 2;
    const int warpCol = wid & 3;
    const int g = lane >> 2, tig = lane & 3;
    const int blockRow = blockIdx.y << 7;
    const int blockCol = blockIdx.x << 7;

    float acc[64];
#pragma unroll
    for (int i = 0; i < 64; ++i) acc[i] = 0.0f;

    const int fr = tid >> 1;
    const int fb = (tid & 1) << 1;
    const half* srcA  = Ah + (size_t)(blockRow + fr) * Kdim + fb * 8;
    const half* srcAl = Al + (size_t)(blockRow + fr) * Kdim + fb * 8;
    const half* srcB  = Bh + (size_t)(blockCol + fr) * Kdim + fb * 8;
    const half* srcBl = Bl + (size_t)(blockCol + fr) * Kdim + fb * 8;
    const uint32_t dstBase = sb0 + fr * 80 + fb * 16;

    const uint32_t loff = (uint32_t)(((lane & 7) + ((lane >> 3) & 1) * 8) * 80
                                     + ((lane >> 4) & 1) * 16);

    const int chunks = Kdim >> 5;

    auto ISSUE = [&](int c) {
        const int s = c & 1;
        const int kh = c << 5;
        uint32_t d = dstBase + s * STAGE_B;
        CPA16(d,              srcA + kh);  CPA16(d + 16,              srcA + kh + 8);
        CPA16(d + TILE_B,     srcAl + kh); CPA16(d + TILE_B + 16,     srcAl + kh + 8);
        CPA16(d + 2 * TILE_B, srcB + kh);  CPA16(d + 2 * TILE_B + 16, srcB + kh + 8);
        CPA16(d + 3 * TILE_B, srcBl + kh); CPA16(d + 3 * TILE_B + 16, srcBl + kh + 8);
    };

    auto COMPUTE = [&](int s) {
        const uint32_t base  = sb0 + s * STAGE_B;
        const uint32_t aBase = base + (warpRow * 64) * 80 + loff;
        const uint32_t bBase = base + 2 * TILE_B + (warpCol * 32) * 80 + loff;
#pragma unroll
        for (int ks = 0; ks < 2; ++ks) {
            const uint32_t kof = ks << 5;
            uint32_t ah[4][4], al[4][4], bh[4][2], bl[4][2];
#pragma unroll
            for (int mt = 0; mt < 4; ++mt) {
                uint32_t ad = aBase + mt * (16 * 80) + kof;
                LDMX4(ah[mt][0], ah[mt][1], ah[mt][2], ah[mt][3], ad);
                LDMX4(al[mt][0], al[mt][1], al[mt][2], al[mt][3], ad + TILE_B);
            }
#pragma unroll
            for (int p = 0; p < 2; ++p) {
                uint32_t bd = bBase + p * (16 * 80) + kof;
                uint32_t r0, r1, r2, r3;
                LDMX4(r0, r1, r2, r3, bd);
                bh[2 * p][0] = r0; bh[2 * p + 1][0] = r1;
                bh[2 * p][1] = r2; bh[2 * p + 1][1] = r3;
                LDMX4(r0, r1, r2, r3, bd + TILE_B);
                bl[2 * p][0] = r0; bl[2 * p + 1][0] = r1;
                bl[2 * p][1] = r2; bl[2 * p + 1][1] = r3;
            }
#pragma unroll
            for (int mt = 0; mt < 4; ++mt)
#pragma unroll
                for (int nt = 0; nt < 4; ++nt)
                    MMA16816(&acc[(mt * 4 + nt) * 4], ah[mt], bh[nt]);
#pragma unroll
            for (int mt = 0; mt < 4; ++mt)
#pragma unroll
                for (int nt = 0; nt < 4; ++nt)
                    MMA16816(&acc[(mt * 4 + nt) * 4], ah[mt], bl[nt]);
#pragma unroll
            for (int mt = 0; mt < 4; ++mt)
#pragma unroll
                for (int nt = 0; nt < 4; ++nt)
                    MMA16816(&acc[(mt * 4 + nt) * 4], al[mt], bh[nt]);
        }
    };

    ISSUE(0);
    CPA_COMMIT();
    for (int c = 0; c < chunks; ++c) {
        CPA_WAIT0();
        __syncthreads();          // chunk c visible to all; stage (c+1)&1 free
        if (c + 1 < chunks) {
            ISSUE(c + 1);
            CPA_COMMIT();
        }
        COMPUTE(c & 1);
    }
    __syncthreads();              // all warps done reading smem before reuse

    // ---- epilogue: stage fp32 acc in smem, then coalesced transform+store
    float* cst = reinterpret_cast<float*>(smem);   // [128][132]
#pragma unroll
    for (int mt = 0; mt < 4; ++mt)
#pragma unroll
        for (int nt = 0; nt < 4; ++nt) {
            const float* a4 = &acc[(mt * 4 + nt) * 4];
            int r0 = (warpRow << 6) + (mt << 4) + g;
            int cc = (warpCol << 5) + (nt << 3) + (tig << 1);
            *reinterpret_cast<float2*>(cst + r0 * 132 + cc) =
                make_float2(a4[0], a4[1]);
            *reinterpret_cast<float2*>(cst + (r0 + 8) * 132 + cc) =
                make_float2(a4[2], a4[3]);
        }
    __syncthreads();
    {
        const int row  = tid >> 1;
        const int colh = (tid & 1) << 6;
        const float* src = cst + row * 132 + colh;
        const size_t gb = (size_t)(blockRow + row) * Mcols + blockCol + colh;
        float ss = 0.0f;
#pragma unroll
        for (int j = 0; j < 16; ++j) {
            float4 v = *reinterpret_cast<const float4*>(src + (j << 2));
            float t0 = tanhf(v.x * OSCALE), t1 = tanhf(v.y * OSCALE);
            float t2 = tanhf(v.z * OSCALE), t3 = tanhf(v.w * OSCALE);
            if (OMODE >= 1) {
                half h0, h1, h2, h3, l0, l1, l2, l3;
                split2(t0 * SCALE_A, h0, l0); split2(t1 * SCALE_A, h1, l1);
                split2(t2 * SCALE_A, h2, l2); split2(t3 * SCALE_A, h3, l3);
                half2 ph0 = __halves2half2(h0, h1), ph1 = __halves2half2(h2, h3);
                half2 pl0 = __halves2half2(l0, l1), pl1 = __halves2half2(l2, l3);
                uint2 uh, ul;
                uh.x = reinterpret_cast<uint32_t&>(ph0);
                uh.y = reinterpret_cast<uint32_t&>(ph1);
                ul.x = reinterpret_cast<uint32_t&>(pl0);
                ul.y = reinterpret_cast<uint32_t&>(pl1);
                *reinterpret_cast<uint2*>(Coh + gb + (j << 2)) = uh;
                *reinterpret_cast<uint2*>(Col + gb + (j << 2)) = ul;
            }
            if (OMODE == 2) {
                ss = fmaf(t0, t0, ss); ss = fmaf(t1, t1, ss);
                ss = fmaf(t2, t2, ss); ss = fmaf(t3, t3, ss);
                float4 o; o.x = t0; o.y = t1; o.z = t2; o.w = t3;
                *reinterpret_cast<float4*>(Cf + gb + (j << 2)) = o;
            }
        }
        // e2 partial per column-block plane (deterministic smem combine)
        if (OMODE == 2) {
            float* e2s = reinterpret_cast<float*>(smem) + 16896;   // past cst
            e2s[tid] = ss;                       // index = row*2 + half
            __syncthreads();
            if ((tid & 1) == 0)
                E2p[(size_t)blockIdx.x * (2 * NTOK) + blockRow + (tid >> 1)] =
                    e2s[tid] + e2s[tid + 1];
        }
    }
}

// ---------------------------------------------------------------------------
// Tensor-core assignment + fused count; single-sync mainloop.
// ---------------------------------------------------------------------------
#define ASSIGN_SMEM 81920

__global__ __launch_bounds__(256)
void assign_mma(const half* __restrict__ Sh, const half* __restrict__ Sl,
                int modal)
{
    extern __shared__ __align__(16) char smem[];
    const uint32_t sb0 = smem_u32(smem);
    const int tid  = threadIdx.x;
    const int lane = tid & 31, wid = tid >> 5;
    const int warpRow = wid >> 2, warpCol = wid & 3;
    const int g = lane >> 2, tig = lane & 3;
    const int rowBase = blockIdx.x << 7;

    const int fr = tid >> 1, fb = (tid & 1) << 1;
    const half* pAh = Sh + (size_t)(rowBase + fr) * SEND + fb * 8;
    const half* pAl = Sl + (size_t)(rowBase + fr) * SEND + fb * 8;
    const uint32_t dAB = sb0 + fr * 80 + fb * 16;

    const uint32_t loff = (uint32_t)(((lane & 7) + ((lane >> 3) & 1) * 8) * 80
                                     + ((lane >> 4) & 1) * 16);

    float e2r[8];
#pragma unroll
    for (int mt = 0; mt < 4; ++mt)
#pragma unroll
        for (int h = 0; h < 2; ++h) {
            int idx = modal * NTOK + rowBase + warpRow * 64 + mt * 16 + g + h * 8;
            e2r[mt * 2 + h] = g_e2p[idx] + g_e2p[2 * NTOK + idx];
        }

    float bestV[8]; int bestI[8];
#pragma unroll
    for (int i = 0; i < 8; ++i) { bestV[i] = 3.4e38f; bestI[i] = 0; }

    float acc[64];
#pragma unroll
    for (int i = 0; i < 64; ++i) acc[i] = 0.0f;

    auto ISSUE = [&](int t) {
        const int ct = t >> 3, c = t & 7;
        const int kh = c << 5;
        uint32_t d = dAB + (uint32_t)(t & 1) * STAGE_B;
        CPA16(d,              pAh + kh); CPA16(d + 16,              pAh + kh + 8);
        CPA16(d + TILE_B,     pAl + kh); CPA16(d + TILE_B + 16,     pAl + kh + 8);
        const half* pBh = g_ch + (size_t)(ct * 128 + fr) * SEND + fb * 8 + kh;
        const half* pBl = g_cl + (size_t)(ct * 128 + fr) * SEND + fb * 8 + kh;
        CPA16(d + 2 * TILE_B, pBh);      CPA16(d + 2 * TILE_B + 16, pBh + 8);
        CPA16(d + 3 * TILE_B, pBl);      CPA16(d + 3 * TILE_B + 16, pBl + 8);
    };

    auto COMPUTE = [&](int s) {
        const uint32_t base  = sb0 + s * STAGE_B;
        const uint32_t aBase = base + (warpRow * 64) * 80 + loff;
        const uint32_t bBase = base + 2 * TILE_B + (warpCol * 32) * 80 + loff;
#pragma unroll
        for (int ks = 0; ks < 2; ++ks) {
            const uint32_t kof = ks << 5;
            uint32_t ah[4][4], al[4][4], bh[4][2], bl[4][2];
#pragma unroll
            for (int mt = 0; mt < 4; ++mt) {
                uint32_t ad = aBase + mt * (16 * 80) + kof;
                LDMX4(ah[mt][0], ah[mt][1], ah[mt][2], ah[mt][3], ad);
                LDMX4(al[mt][0], al[mt][1], al[mt][2], al[mt][3], ad + TILE_B);
            }
#pragma unroll
            for (int p = 0; p < 2; ++p) {
                uint32_t bd = bBase + p * (16 * 80) + kof;
                uint32_t r0, r1, r2, r3;
                LDMX4(r0, r1, r2, r3, bd);
                bh[2 * p][0] = r0; bh[2 * p + 1][0] = r1;
                bh[2 * p][1] = r2; bh[2 * p + 1][1] = r3;
                LDMX4(r0, r1, r2, r3, bd + TILE_B);
                bl[2 * p][0] = r0; bl[2 * p + 1][0] = r1;
                bl[2 * p][1] = r2; bl[2 * p + 1][1] = r3;
            }
#pragma unroll
            for (int mt = 0; mt < 4; ++mt)
#pragma unroll
                for (int nt = 0; nt < 4; ++nt)
                    MMA16816(&acc[(mt * 4 + nt) * 4], ah[mt], bh[nt]);
#pragma unroll
            for (int mt = 0; mt < 4; ++mt)
#pragma unroll
                for (int nt = 0; nt < 4; ++nt)
                    MMA16816(&acc[(mt * 4 + nt) * 4], ah[mt], bl[nt]);
#pragma unroll
            for (int mt = 0; mt < 4; ++mt)
#pragma unroll
                for (int nt = 0; nt < 4; ++nt)
                    MMA16816(&acc[(mt * 4 + nt) * 4], al[mt], bh[nt]);
        }
    };

    ISSUE(0);
    CPA_COMMIT();
    for (int t = 0; t < 32; ++t) {
        CPA_WAIT0();
        __syncthreads();
        if (t + 1 < 32) {
            ISSUE(t + 1);
            CPA_COMMIT();
        }
        COMPUTE(t & 1);

        if ((t & 7) == 7) {               // registers + const global only
            const int ct = t >> 3;
#pragma unroll
            for (int nt = 0; nt < 4; ++nt)
#pragma unroll
                for (int j = 0; j < 2; ++j) {
                    int col = ct * 128 + warpCol * 32 + nt * 8 + tig * 2 + j;
                    float c2v = g_c2[col];
#pragma unroll
                    for (int mt = 0; mt < 4; ++mt)
#pragma unroll
                        for (int h = 0; h < 2; ++h) {
                            float s = (c2v + e2r[mt * 2 + h]) -
                                2.0f * (acc[(mt * 4 + nt) * 4 + h * 2 + j] * OSCALE);
                            int bi = mt * 2 + h;
                            if (s < bestV[bi] ||
                                (s == bestV[bi] && col < bestI[bi])) {
                                bestV[bi] = s; bestI[bi] = col;
                            }
                        }
                }
#pragma unroll
            for (int i = 0; i < 64; ++i) acc[i] = 0.0f;
        }
    }
    __syncthreads();

    // ---- cross-thread reduction (16 slots per row) + fused count
    float (*rv)[16] = reinterpret_cast<float(*)[16]>(smem);
    int   (*ri)[16] = reinterpret_cast<int(*)[16]>(smem + 8192);
    const int slot = warpCol * 4 + tig;
#pragma unroll
    for (int mt = 0; mt < 4; ++mt)
#pragma unroll
        for (int h = 0; h < 2; ++h) {
            int row = warpRow * 64 + mt * 16 + g + h * 8;
            rv[row][slot] = bestV[mt * 2 + h];
            ri[row][slot] = bestI[mt * 2 + h];
        }
    __syncthreads();
    if (tid < 128) {
        float bv = rv[tid][0]; int bi = ri[tid][0];
#pragma unroll
        for (int u = 1; u < 16; ++u) {
            float v = rv[tid][u]; int ix = ri[tid][u];
            if (v < bv || (v == bv && ix < bi)) { bv = v; bi = ix; }
        }
        g_sc[modal * NTOK + rowBase + tid] = bi;
        atomicAdd(&g_counts[modal * KC + bi], 1);
    }
}

// ---------------------------------------------------------------------------
// emb fp32 -> (hi, lo) halves, scaled
// ---------------------------------------------------------------------------
__global__ void split_src(const float* __restrict__ X,
                          half* __restrict__ Xh, half* __restrict__ Xl)
{
    int i = blockIdx.x * blockDim.x + threadIdx.x;
    float4 v = reinterpret_cast<const float4*>(X)[i];
    half h0, h1, h2, h3, l0, l1, l2, l3;
    split2(v.x * SCALE_A, h0, l0); split2(v.y * SCALE_A, h1, l1);
    split2(v.z * SCALE_A, h2, l2); split2(v.w * SCALE_A, h3, l3);
    half2 ph0 = __halves2half2(h0, h1), ph1 = __halves2half2(h2, h3);
    half2 pl0 = __halves2half2(l0, l1), pl1 = __halves2half2(l2, l3);
    uint2 uh, ul;
    uh.x = reinterpret_cast<uint32_t&>(ph0); uh.y = reinterpret_cast<uint32_t&>(ph1);
    ul.x = reinterpret_cast<uint32_t&>(pl0); ul.y = reinterpret_cast<uint32_t&>(pl1);
    reinterpret_cast<uint2*>(Xh)[i] = uh;
    reinterpret_cast<uint2*>(Xl)[i] = ul;
}

// ---------------------------------------------------------------------------
// All 6 weight transposes + splits in one launch.
// ---------------------------------------------------------------------------
__global__ void transpose_split_all(
    const float* __restrict__ W10, const float* __restrict__ W20,
    const float* __restrict__ W30, const float* __restrict__ W11,
    const float* __restrict__ W21, const float* __restrict__ W31)
{
    const int z = blockIdx.z;
    const int m = z / 3, layer = z % 3;
    const int N = (layer == 2) ? SEND : HIDD;
    if ((blockIdx.x << 5) >= N) return;

    const float* W =
        (layer == 0) ? (m ? W11 : W10) :
        (layer == 1) ? (m ? W21 : W20) : (m ? W31 : W30);
    half* Th = (layer == 0) ? g_w1h[m] : (layer == 1) ? g_w2h[m] : g_w3h[m];
    half* Tl = (layer == 0) ? g_w1l[m] : (layer == 1) ? g_w2l[m] : g_w3l[m];

    __shared__ float t[32][33];
    const int bx = blockIdx.x << 5;   // n base
    const int by = blockIdx.y << 5;   // k base
#pragma unroll
    for (int j = 0; j < 32; j += 8)
        t[threadIdx.y + j][threadIdx.x] =
            W[(size_t)(by + threadIdx.y + j) * N + bx + threadIdx.x];
    __syncthreads();
#pragma unroll
    for (int j = 0; j < 32; j += 8) {
        float f = t[threadIdx.x][threadIdx.y + j] * SCALE_B;
        half h, l;
        split2(f, h, l);
        size_t o = (size_t)(bx + threadIdx.y + j) * HIDD + by + threadIdx.x;
        Th[o] = h;
        Tl[o] = l;
    }
}

// ---------------------------------------------------------------------------
// Fused centroid prep: tanh -> d_out, split halves, c2 sumsq, zero counts.
// 64 blocks x 256 threads; warp w of block b handles centroid row b*8+w.
// ---------------------------------------------------------------------------
__global__ void centroid_prep(const float* __restrict__ raw, float* __restrict__ out)
{
    const int tid  = threadIdx.x;
    const int lane = tid & 31;
    const int row  = blockIdx.x * 8 + (tid >> 5);
    const int gtid = blockIdx.x * 256 + tid;
    if (gtid < 2 * KC) g_counts[gtid] = 0;

    const float* src = raw + (size_t)row * SEND;
    float ss = 0.0f;
#pragma unroll
    for (int j = 0; j < 8; ++j) {
        int idx = lane + j * 32;
        float t = tanhf(src[idx]);
        out[CENT_OFF + (size_t)row * SEND + idx] = t;
        half h, l;
        split2(t * SCALE_B, h, l);
        g_ch[(size_t)row * SEND + idx] = h;
        g_cl[(size_t)row * SEND + idx] = l;
        ss = fmaf(t, t, ss);
    }
#pragma unroll
    for (int o = 16; o > 0; o >>= 1) ss += __shfl_xor_sync(0xffffffffu, ss, o);
    if (lane == 0) g_c2[row] = ss;
}

// ---------------------------------------------------------------------------
// Counting sort (stable)
// ---------------------------------------------------------------------------
__global__ void scan_kernel(int modal)
{
    __shared__ int tmp[KC];
    int t = threadIdx.x;
    int v = g_counts[modal * KC + t];
    tmp[t] = v;
    __syncthreads();
    for (int off = 1; off < KC; off <<= 1) {
        int x = (t >= off) ? tmp[t - off] : 0;
        __syncthreads();
        tmp[t] += x;
        __syncthreads();
    }
    g_offsets[modal * KC + t] = tmp[t] - v;
}

__global__ void scatter_kernel(int modal, float* __restrict__ order)
{
    const int k = blockIdx.x;
    const int base0 = modal * NTOK;
    __shared__ int warpTot[8];
    int base = g_offsets[modal * KC + k];
    int lane = threadIdx.x & 31, wid = threadIdx.x >> 5;

    for (int start = 0; start < NTOK; start += 256) {
        int i = start + threadIdx.x;
        bool m = (g_sc[base0 + i] == k);
        unsigned b = __ballot_sync(0xffffffffu, m);
        if (lane == 0) warpTot[wid] = __popc(b);
        __syncthreads();
        int woff = 0, tot = 0;
#pragma unroll
        for (int w = 0; w < 8; ++w) { int c = warpTot[w]; tot += c; if (w < wid) woff += c; }
        if (m) order[base + woff + __popc(b & ((1u << lane) - 1u))] = (float)i;
        base += tot;
        __syncthreads();
    }
}

// ---------------------------------------------------------------------------
// word_class / sense_class / counts (fused)
// ---------------------------------------------------------------------------
__global__ void finalize_kernel(float* __restrict__ out)
{
    int i = blockIdx.x * blockDim.x + threadIdx.x;
    out[WC_OFF + i]  = (i < NTOK) ? 0.0f : 1.0f;
    out[SCL_OFF + i] = (float)g_sc[i];
    if (i < 2 * KC) {
        int m = i >> 9, k = i & 511;
        out[(m ? CI_OFF : CT_OFF) + k] = (float)g_counts[i];
    }
}

// ---------------------------------------------------------------------------
// Launch
// ---------------------------------------------------------------------------
extern "C" void kernel_launch(void* const* d_in, const int* in_sizes, int n_in,
                              void* d_out, int out_size)
{
    const float* emb[2] = { (const float*)d_in[0], (const float*)d_in[1] };
    const float* W1[2]  = { (const float*)d_in[2], (const float*)d_in[5] };
    const float* W2[2]  = { (const float*)d_in[3], (const float*)d_in[6] };
    const float* W3[2]  = { (const float*)d_in[4], (const float*)d_in[7] };
    const float* craw   = (const float*)d_in[8];
    float* out = (float*)d_out;

    half *xh1, *xl1, *xh2, *xl2;
    half *w1h, *w1l, *w2h, *w2l, *w3h, *w3l;
    float* e2p;
    cudaGetSymbolAddress((void**)&xh1, g_xh1);
    cudaGetSymbolAddress((void**)&xl1, g_xl1);
    cudaGetSymbolAddress((void**)&xh2, g_xh2);
    cudaGetSymbolAddress((void**)&xl2, g_xl2);
    cudaGetSymbolAddress((void**)&w1h, g_w1h);
    cudaGetSymbolAddress((void**)&w1l, g_w1l);
    cudaGetSymbolAddress((void**)&w2h, g_w2h);
    cudaGetSymbolAddress((void**)&w2l, g_w2l);
    cudaGetSymbolAddress((void**)&w3h, g_w3h);
    cudaGetSymbolAddress((void**)&w3l, g_w3l);
    cudaGetSymbolAddress((void**)&e2p, g_e2p);

    cudaFuncSetAttribute(gemm_split<1>,
                         cudaFuncAttributeMaxDynamicSharedMemorySize, GEMM_SMEM);
    cudaFuncSetAttribute(gemm_split<2>,
                         cudaFuncAttributeMaxDynamicSharedMemorySize, GEMM_SMEM);
    cudaFuncSetAttribute(assign_mma,
                         cudaFuncAttributeMaxDynamicSharedMemorySize, ASSIGN_SMEM);

    centroid_prep<<<KC / 8, 256>>>(craw, out);
    transpose_split_all<<<dim3(32, 32, 6), dim3(32, 8)>>>(
        W1[0], W2[0], W3[0], W1[1], W2[1], W3[1]);

    const size_t WSZ = (size_t)HIDD * HIDD;
    const size_t W3SZ = (size_t)SEND * HIDD;

    for (int m = 0; m < 2; ++m) {
        float* se = out + SE_OFF + (size_t)m * NTOK * SEND;

        split_src<<<(NTOK * TOKD / 4) / 256, 256>>>(emb[m], xh1, xl1);

        gemm_split<1><<<dim3(HIDD / 128, NTOK / 128), 256, GEMM_SMEM>>>(
            xh1, xl1, w1h + m * WSZ, w1l + m * WSZ,
            nullptr, xh2, xl2, nullptr, TOKD, HIDD);

        gemm_split<1><<<dim3(HIDD / 128, NTOK / 128), 256, GEMM_SMEM>>>(
            xh2, xl2, w2h + m * WSZ, w2l + m * WSZ,
            nullptr, xh1, xl1, nullptr, HIDD, HIDD);

        gemm_split<2><<<dim3(SEND / 128, NTOK / 128), 256, GEMM_SMEM>>>(
            xh1, xl1, w3h + m * W3SZ, w3l + m * W3SZ,
            se, xh2, xl2, e2p + (size_t)m * NTOK, HIDD, SEND);

        assign_mma<<<NTOK / 128, 256, ASSIGN_SMEM>>>(xh2, xl2, m);

        scan_kernel<<<1, KC>>>(m);
        scatter_kernel<<<KC, 256>>>(m, out + (m ? OI_OFF : OT_OFF));
    }

    finalize_kernel<<<(2 * NTOK) / 256, 256>>>(out);
}

// round 14
// speedup vs baseline: 2.0564x; 1.0376x over previous
#include <cuda_runtime.h>
#include <cuda_fp16.h>
#include <math.h>
#include <stdint.h>

// ---------------------------------------------------------------------------
// Problem constants
// ---------------------------------------------------------------------------
#define NTOK 32768
#define TOKD 1024
#define HIDD 1024
#define SEND 256
#define KC   512

// d_out float offsets (flattened reference tuple, fp32)
#define CENT_OFF 0
#define SE_OFF   131072
#define WC_OFF   16908288
#define SCL_OFF  16973824
#define OT_OFF   17039360
#define CT_OFF   17072128
#define OI_OFF   17072640
#define CI_OFF   17105408

#define SCALE_A 16.0f
#define SCALE_B 64.0f
#define OSCALE  (1.0f / 1024.0f)

#define ASLAB ((size_t)NTOK * HIDD)      // per-modal activation slab (elements)

// ---------------------------------------------------------------------------
// Scratch (device globals) — per-modal activation slabs for merged launches
// ---------------------------------------------------------------------------
__device__ half  g_xh1[2][ASLAB];
__device__ half  g_xl1[2][ASLAB];
__device__ half  g_xh2[2][ASLAB];
__device__ half  g_xl2[2][ASLAB];
__device__ half  g_w1h[2][(size_t)HIDD * HIDD];   // transposed weights, N-major
__device__ half  g_w1l[2][(size_t)HIDD * HIDD];
__device__ half  g_w2h[2][(size_t)HIDD * HIDD];
__device__ half  g_w2l[2][(size_t)HIDD * HIDD];
__device__ half  g_w3h[2][(size_t)SEND * HIDD];
__device__ half  g_w3l[2][(size_t)SEND * HIDD];
__device__ half  g_ch[(size_t)KC * SEND];         // centroids hi (x64)
__device__ half  g_cl[(size_t)KC * SEND];         // centroids lo
__device__ float g_c2[KC];
__device__ float g_e2p[4 * NTOK];                 // [plane(2)][modal(2)][NTOK]
__device__ int   g_sc[2 * NTOK];
__device__ int   g_counts[2 * KC];
__device__ int   g_offsets[2 * KC];

// ---------------------------------------------------------------------------
// PTX helpers (sm_80-era, portable under compute_100)
// ---------------------------------------------------------------------------
__device__ __forceinline__ uint32_t smem_u32(const void* p) {
    uint32_t a;
    asm("{ .reg .u64 t; cvta.to.shared.u64 t, %1; cvt.u32.u64 %0, t; }"
        : "=r"(a) : "l"(p));
    return a;
}

#define MMA16816(d, a, b) \
    asm volatile( \
        "mma.sync.aligned.m16n8k16.row.col.f32.f16.f16.f32 " \
        "{%0,%1,%2,%3}, {%4,%5,%6,%7}, {%8,%9}, {%0,%1,%2,%3};" \
        : "+f"((d)[0]), "+f"((d)[1]), "+f"((d)[2]), "+f"((d)[3]) \
        : "r"((a)[0]), "r"((a)[1]), "r"((a)[2]), "r"((a)[3]), \
          "r"((b)[0]), "r"((b)[1]))

#define LDMX4(r0, r1, r2, r3, addr) \
    asm volatile("ldmatrix.sync.aligned.m8n8.x4.shared.b16 {%0,%1,%2,%3}, [%4];" \
        : "=r"(r0), "=r"(r1), "=r"(r2), "=r"(r3) : "r"(addr))

#define CPA16(dst, src) \
    asm volatile("cp.async.ca.shared.global [%0], [%1], 16;" :: "r"(dst), "l"(src))
#define CPA_COMMIT() asm volatile("cp.async.commit_group;")
#define CPA_WAIT0()  asm volatile("cp.async.wait_group 0;")

__device__ __forceinline__ void split2(float f, half& h, half& l) {
    h = __float2half_rn(f);
    l = __float2half_rn(f - __half2float(h));
}

// ---------------------------------------------------------------------------
// fp16x3 split-GEMM, both modals per launch (z = modal).
// Single-sync mainloop; COMPUTE interleaves fragment loads with MMA groups
// (group order ah*bh, ah*bl, al*bh preserved -> bit-identical accumulation).
// OMODE: 1 = split (hi,lo)*SCALE_A out; 2 = fp32 out + split out + e2 partials.
// ---------------------------------------------------------------------------
#define TILE_B    10240         // 128 rows * 80 B
#define STAGE_B   40960         // Ah | Al | Bh | Bl tiles
#define GEMM_SMEM 81920         // 2 stages

template<int OMODE>
__global__ __launch_bounds__(256)
void gemm_split(const half* __restrict__ AhG, const half* __restrict__ AlG,
                size_t aStr,
                const half* __restrict__ BhG, const half* __restrict__ BlG,
                size_t bStr,
                float* __restrict__ CfG, size_t cfStr,
                half* __restrict__ CohG, half* __restrict__ ColG, size_t coStr,
                float* __restrict__ E2p,
                int Kdim, int Mcols)
{
    extern __shared__ __align__(16) char smem[];
    const uint32_t sb0 = smem_u32(smem);

    const int z = blockIdx.z;
    const half* Ah = AhG + (size_t)z * aStr;
    const half* Al = AlG + (size_t)z * aStr;
    const half* Bh = BhG + (size_t)z * bStr;
    const half* Bl = BlG + (size_t)z * bStr;

    const int tid  = threadIdx.x;
    const int lane = tid & 31, wid = tid >> 5;
    const int warpRow = wid >> 2;
    const int warpCol = wid & 3;
    const int g = lane >> 2, tig = lane & 3;
    const int blockRow = blockIdx.y << 7;
    const int blockCol = blockIdx.x << 7;

    float acc[64];
#pragma unroll
    for (int i = 0; i < 64; ++i) acc[i] = 0.0f;

    const int fr = tid >> 1;
    const int fb = (tid & 1) << 1;
    const half* srcA  = Ah + (size_t)(blockRow + fr) * Kdim + fb * 8;
    const half* srcAl = Al + (size_t)(blockRow + fr) * Kdim + fb * 8;
    const half* srcB  = Bh + (size_t)(blockCol + fr) * Kdim + fb * 8;
    const half* srcBl = Bl + (size_t)(blockCol + fr) * Kdim + fb * 8;
    const uint32_t dstBase = sb0 + fr * 80 + fb * 16;

    const uint32_t loff = (uint32_t)(((lane & 7) + ((lane >> 3) & 1) * 8) * 80
                                     + ((lane >> 4) & 1) * 16);

    const int chunks = Kdim >> 5;

    auto ISSUE = [&](int c) {
        const int s = c & 1;
        const int kh = c << 5;
        uint32_t d = dstBase + s * STAGE_B;
        CPA16(d,              srcA + kh);  CPA16(d + 16,              srcA + kh + 8);
        CPA16(d + TILE_B,     srcAl + kh); CPA16(d + TILE_B + 16,     srcAl + kh + 8);
        CPA16(d + 2 * TILE_B, srcB + kh);  CPA16(d + 2 * TILE_B + 16, srcB + kh + 8);
        CPA16(d + 3 * TILE_B, srcBl + kh); CPA16(d + 3 * TILE_B + 16, srcBl + kh + 8);
    };

    auto COMPUTE = [&](int s) {
        const uint32_t base  = sb0 + s * STAGE_B;
        const uint32_t aBase = base + (warpRow * 64) * 80 + loff;
        const uint32_t bBase = base + 2 * TILE_B + (warpCol * 32) * 80 + loff;
#pragma unroll
        for (int ks = 0; ks < 2; ++ks) {
            const uint32_t kof = ks << 5;
            uint32_t ah[4][4], al[4][4], bh[4][2], bl[4][2];
            // -- load ah + bh, run group 1 (ah*bh)
#pragma unroll
            for (int mt = 0; mt < 4; ++mt) {
                uint32_t ad = aBase + mt * (16 * 80) + kof;
                LDMX4(ah[mt][0], ah[mt][1], ah[mt][2], ah[mt][3], ad);
            }
#pragma unroll
            for (int p = 0; p < 2; ++p) {
                uint32_t bd = bBase + p * (16 * 80) + kof;
                uint32_t r0, r1, r2, r3;
                LDMX4(r0, r1, r2, r3, bd);
                bh[2 * p][0] = r0; bh[2 * p + 1][0] = r1;
                bh[2 * p][1] = r2; bh[2 * p + 1][1] = r3;
            }
#pragma unroll
            for (int mt = 0; mt < 4; ++mt)
#pragma unroll
                for (int nt = 0; nt < 4; ++nt)
                    MMA16816(&acc[(mt * 4 + nt) * 4], ah[mt], bh[nt]);
            // -- load bl, run group 2 (ah*bl)
#pragma unroll
            for (int p = 0; p < 2; ++p) {
                uint32_t bd = bBase + p * (16 * 80) + kof + TILE_B;
                uint32_t r0, r1, r2, r3;
                LDMX4(r0, r1, r2, r3, bd);
                bl[2 * p][0] = r0; bl[2 * p + 1][0] = r1;
                bl[2 * p][1] = r2; bl[2 * p + 1][1] = r3;
            }
#pragma unroll
            for (int mt = 0; mt < 4; ++mt)
#pragma unroll
                for (int nt = 0; nt < 4; ++nt)
                    MMA16816(&acc[(mt * 4 + nt) * 4], ah[mt], bl[nt]);
            // -- load al, run group 3 (al*bh)
#pragma unroll
            for (int mt = 0; mt < 4; ++mt) {
                uint32_t ad = aBase + mt * (16 * 80) + kof + TILE_B;
                LDMX4(al[mt][0], al[mt][1], al[mt][2], al[mt][3], ad);
            }
#pragma unroll
            for (int mt = 0; mt < 4; ++mt)
#pragma unroll
                for (int nt = 0; nt < 4; ++nt)
                    MMA16816(&acc[(mt * 4 + nt) * 4], al[mt], bh[nt]);
        }
    };

    ISSUE(0);
    CPA_COMMIT();
    for (int c = 0; c < chunks; ++c) {
        CPA_WAIT0();
        __syncthreads();          // chunk c visible; stage (c+1)&1 free
        if (c + 1 < chunks) {
            ISSUE(c + 1);
            CPA_COMMIT();
        }
        COMPUTE(c & 1);
    }
    __syncthreads();

    // ---- epilogue: stage fp32 acc in smem, then coalesced transform+store
    float* cst = reinterpret_cast<float*>(smem);   // [128][132]
#pragma unroll
    for (int mt = 0; mt < 4; ++mt)
#pragma unroll
        for (int nt = 0; nt < 4; ++nt) {
            const float* a4 = &acc[(mt * 4 + nt) * 4];
            int r0 = (warpRow << 6) + (mt << 4) + g;
            int cc = (warpCol << 5) + (nt << 3) + (tig << 1);
            *reinterpret_cast<float2*>(cst + r0 * 132 + cc) =
                make_float2(a4[0], a4[1]);
            *reinterpret_cast<float2*>(cst + (r0 + 8) * 132 + cc) =
                make_float2(a4[2], a4[3]);
        }
    __syncthreads();
    {
        half*  Coh = CohG + (size_t)z * coStr;
        half*  Col = ColG + (size_t)z * coStr;
        const int row  = tid >> 1;
        const int colh = (tid & 1) << 6;
        const float* src = cst + row * 132 + colh;
        const size_t gb = (size_t)(blockRow + row) * Mcols + blockCol + colh;
        float ss = 0.0f;
#pragma unroll
        for (int j = 0; j < 16; ++j) {
            float4 v = *reinterpret_cast<const float4*>(src + (j << 2));
            float t0 = tanhf(v.x * OSCALE), t1 = tanhf(v.y * OSCALE);
            float t2 = tanhf(v.z * OSCALE), t3 = tanhf(v.w * OSCALE);
            if (OMODE >= 1) {
                half h0, h1, h2, h3, l0, l1, l2, l3;
                split2(t0 * SCALE_A, h0, l0); split2(t1 * SCALE_A, h1, l1);
                split2(t2 * SCALE_A, h2, l2); split2(t3 * SCALE_A, h3, l3);
                half2 ph0 = __halves2half2(h0, h1), ph1 = __halves2half2(h2, h3);
                half2 pl0 = __halves2half2(l0, l1), pl1 = __halves2half2(l2, l3);
                uint2 uh, ul;
                uh.x = reinterpret_cast<uint32_t&>(ph0);
                uh.y = reinterpret_cast<uint32_t&>(ph1);
                ul.x = reinterpret_cast<uint32_t&>(pl0);
                ul.y = reinterpret_cast<uint32_t&>(pl1);
                *reinterpret_cast<uint2*>(Coh + gb + (j << 2)) = uh;
                *reinterpret_cast<uint2*>(Col + gb + (j << 2)) = ul;
            }
            if (OMODE == 2) {
                ss = fmaf(t0, t0, ss); ss = fmaf(t1, t1, ss);
                ss = fmaf(t2, t2, ss); ss = fmaf(t3, t3, ss);
                float4 o; o.x = t0; o.y = t1; o.z = t2; o.w = t3;
                *reinterpret_cast<float4*>(CfG + (size_t)z * cfStr + gb + (j << 2)) = o;
            }
        }
        if (OMODE == 2) {
            float* e2s = reinterpret_cast<float*>(smem) + 16896;   // past cst
            e2s[tid] = ss;
            __syncthreads();
            if ((tid & 1) == 0)
                E2p[(size_t)blockIdx.x * (2 * NTOK) + (size_t)z * NTOK
                    + blockRow + (tid >> 1)] = e2s[tid] + e2s[tid + 1];
        }
    }
}

// ---------------------------------------------------------------------------
// Tensor-core assignment, both modals (y = modal); fused count.
// ---------------------------------------------------------------------------
#define ASSIGN_SMEM 81920

__global__ __launch_bounds__(256)
void assign_mma(const half* __restrict__ ShG, const half* __restrict__ SlG)
{
    extern __shared__ __align__(16) char smem[];
    const uint32_t sb0 = smem_u32(smem);
    const int modal = blockIdx.y;
    const half* Sh = ShG + (size_t)modal * ASLAB;
    const half* Sl = SlG + (size_t)modal * ASLAB;

    const int tid  = threadIdx.x;
    const int lane = tid & 31, wid = tid >> 5;
    const int warpRow = wid >> 2, warpCol = wid & 3;
    const int g = lane >> 2, tig = lane & 3;
    const int rowBase = blockIdx.x << 7;

    const int fr = tid >> 1, fb = (tid & 1) << 1;
    const half* pAh = Sh + (size_t)(rowBase + fr) * SEND + fb * 8;
    const half* pAl = Sl + (size_t)(rowBase + fr) * SEND + fb * 8;
    const uint32_t dAB = sb0 + fr * 80 + fb * 16;

    const uint32_t loff = (uint32_t)(((lane & 7) + ((lane >> 3) & 1) * 8) * 80
                                     + ((lane >> 4) & 1) * 16);

    float e2r[8];
#pragma unroll
    for (int mt = 0; mt < 4; ++mt)
#pragma unroll
        for (int h = 0; h < 2; ++h) {
            int idx = modal * NTOK + rowBase + warpRow * 64 + mt * 16 + g + h * 8;
            e2r[mt * 2 + h] = g_e2p[idx] + g_e2p[2 * NTOK + idx];
        }

    float bestV[8]; int bestI[8];
#pragma unroll
    for (int i = 0; i < 8; ++i) { bestV[i] = 3.4e38f; bestI[i] = 0; }

    float acc[64];
#pragma unroll
    for (int i = 0; i < 64; ++i) acc[i] = 0.0f;

    auto ISSUE = [&](int t) {
        const int ct = t >> 3, c = t & 7;
        const int kh = c << 5;
        uint32_t d = dAB + (uint32_t)(t & 1) * STAGE_B;
        CPA16(d,              pAh + kh); CPA16(d + 16,              pAh + kh + 8);
        CPA16(d + TILE_B,     pAl + kh); CPA16(d + TILE_B + 16,     pAl + kh + 8);
        const half* pBh = g_ch + (size_t)(ct * 128 + fr) * SEND + fb * 8 + kh;
        const half* pBl = g_cl + (size_t)(ct * 128 + fr) * SEND + fb * 8 + kh;
        CPA16(d + 2 * TILE_B, pBh);      CPA16(d + 2 * TILE_B + 16, pBh + 8);
        CPA16(d + 3 * TILE_B, pBl);      CPA16(d + 3 * TILE_B + 16, pBl + 8);
    };

    auto COMPUTE = [&](int s) {
        const uint32_t base  = sb0 + s * STAGE_B;
        const uint32_t aBase = base + (warpRow * 64) * 80 + loff;
        const uint32_t bBase = base + 2 * TILE_B + (warpCol * 32) * 80 + loff;
#pragma unroll
        for (int ks = 0; ks < 2; ++ks) {
            const uint32_t kof = ks << 5;
            uint32_t ah[4][4], al[4][4], bh[4][2], bl[4][2];
#pragma unroll
            for (int mt = 0; mt < 4; ++mt) {
                uint32_t ad = aBase + mt * (16 * 80) + kof;
                LDMX4(ah[mt][0], ah[mt][1], ah[mt][2], ah[mt][3], ad);
            }
#pragma unroll
            for (int p = 0; p < 2; ++p) {
                uint32_t bd = bBase + p * (16 * 80) + kof;
                uint32_t r0, r1, r2, r3;
                LDMX4(r0, r1, r2, r3, bd);
                bh[2 * p][0] = r0; bh[2 * p + 1][0] = r1;
                bh[2 * p][1] = r2; bh[2 * p + 1][1] = r3;
            }
#pragma unroll
            for (int mt = 0; mt < 4; ++mt)
#pragma unroll
                for (int nt = 0; nt < 4; ++nt)
                    MMA16816(&acc[(mt * 4 + nt) * 4], ah[mt], bh[nt]);
#pragma unroll
            for (int p = 0; p < 2; ++p) {
                uint32_t bd = bBase + p * (16 * 80) + kof + TILE_B;
                uint32_t r0, r1, r2, r3;
                LDMX4(r0, r1, r2, r3, bd);
                bl[2 * p][0] = r0; bl[2 * p + 1][0] = r1;
                bl[2 * p][1] = r2; bl[2 * p + 1][1] = r3;
            }
#pragma unroll
            for (int mt = 0; mt < 4; ++mt)
#pragma unroll
                for (int nt = 0; nt < 4; ++nt)
                    MMA16816(&acc[(mt * 4 + nt) * 4], ah[mt], bl[nt]);
#pragma unroll
            for (int mt = 0; mt < 4; ++mt) {
                uint32_t ad = aBase + mt * (16 * 80) + kof + TILE_B;
                LDMX4(al[mt][0], al[mt][1], al[mt][2], al[mt][3], ad);
            }
#pragma unroll
            for (int mt = 0; mt < 4; ++mt)
#pragma unroll
                for (int nt = 0; nt < 4; ++nt)
                    MMA16816(&acc[(mt * 4 + nt) * 4], al[mt], bh[nt]);
        }
    };

    ISSUE(0);
    CPA_COMMIT();
    for (int t = 0; t < 32; ++t) {
        CPA_WAIT0();
        __syncthreads();
        if (t + 1 < 32) {
            ISSUE(t + 1);
            CPA_COMMIT();
        }
        COMPUTE(t & 1);

        if ((t & 7) == 7) {               // registers + const global only
            const int ct = t >> 3;
#pragma unroll
            for (int nt = 0; nt < 4; ++nt)
#pragma unroll
                for (int j = 0; j < 2; ++j) {
                    int col = ct * 128 + warpCol * 32 + nt * 8 + tig * 2 + j;
                    float c2v = g_c2[col];
#pragma unroll
                    for (int mt = 0; mt < 4; ++mt)
#pragma unroll
                        for (int h = 0; h < 2; ++h) {
                            float s = (c2v + e2r[mt * 2 + h]) -
                                2.0f * (acc[(mt * 4 + nt) * 4 + h * 2 + j] * OSCALE);
                            int bi = mt * 2 + h;
                            if (s < bestV[bi] ||
                                (s == bestV[bi] && col < bestI[bi])) {
                                bestV[bi] = s; bestI[bi] = col;
                            }
                        }
                }
#pragma unroll
            for (int i = 0; i < 64; ++i) acc[i] = 0.0f;
        }
    }
    __syncthreads();

    // ---- cross-thread reduction (16 slots per row) + fused count
    float (*rv)[16] = reinterpret_cast<float(*)[16]>(smem);
    int   (*ri)[16] = reinterpret_cast<int(*)[16]>(smem + 8192);
    const int slot = warpCol * 4 + tig;
#pragma unroll
    for (int mt = 0; mt < 4; ++mt)
#pragma unroll
        for (int h = 0; h < 2; ++h) {
            int row = warpRow * 64 + mt * 16 + g + h * 8;
            rv[row][slot] = bestV[mt * 2 + h];
            ri[row][slot] = bestI[mt * 2 + h];
        }
    __syncthreads();
    if (tid < 128) {
        float bv = rv[tid][0]; int bi = ri[tid][0];
#pragma unroll
        for (int u = 1; u < 16; ++u) {
            float v = rv[tid][u]; int ix = ri[tid][u];
            if (v < bv || (v == bv && ix < bi)) { bv = v; bi = ix; }
        }
        g_sc[modal * NTOK + rowBase + tid] = bi;
        atomicAdd(&g_counts[modal * KC + bi], 1);
    }
}

// ---------------------------------------------------------------------------
// emb fp32 -> (hi, lo) halves, scaled — both modals (y = modal)
// ---------------------------------------------------------------------------
__global__ void split_src(const float* __restrict__ X0,
                          const float* __restrict__ X1,
                          half* __restrict__ XhG, half* __restrict__ XlG)
{
    const int m = blockIdx.y;
    const float* X = m ? X1 : X0;
    half* Xh = XhG + (size_t)m * ASLAB;
    half* Xl = XlG + (size_t)m * ASLAB;
    int i = blockIdx.x * blockDim.x + threadIdx.x;
    float4 v = reinterpret_cast<const float4*>(X)[i];
    half h0, h1, h2, h3, l0, l1, l2, l3;
    split2(v.x * SCALE_A, h0, l0); split2(v.y * SCALE_A, h1, l1);
    split2(v.z * SCALE_A, h2, l2); split2(v.w * SCALE_A, h3, l3);
    half2 ph0 = __halves2half2(h0, h1), ph1 = __halves2half2(h2, h3);
    half2 pl0 = __halves2half2(l0, l1), pl1 = __halves2half2(l2, l3);
    uint2 uh, ul;
    uh.x = reinterpret_cast<uint32_t&>(ph0); uh.y = reinterpret_cast<uint32_t&>(ph1);
    ul.x = reinterpret_cast<uint32_t&>(pl0); ul.y = reinterpret_cast<uint32_t&>(pl1);
    reinterpret_cast<uint2*>(Xh)[i] = uh;
    reinterpret_cast<uint2*>(Xl)[i] = ul;
}

// ---------------------------------------------------------------------------
// All 6 weight transposes + splits in one launch.
// ---------------------------------------------------------------------------
__global__ void transpose_split_all(
    const float* __restrict__ W10, const float* __restrict__ W20,
    const float* __restrict__ W30, const float* __restrict__ W11,
    const float* __restrict__ W21, const float* __restrict__ W31)
{
    const int z = blockIdx.z;
    const int m = z / 3, layer = z % 3;
    const int N = (layer == 2) ? SEND : HIDD;
    if ((blockIdx.x << 5) >= N) return;

    const float* W =
        (layer == 0) ? (m ? W11 : W10) :
        (layer == 1) ? (m ? W21 : W20) : (m ? W31 : W30);
    half* Th = (layer == 0) ? g_w1h[m] : (layer == 1) ? g_w2h[m] : g_w3h[m];
    half* Tl = (layer == 0) ? g_w1l[m] : (layer == 1) ? g_w2l[m] : g_w3l[m];

    __shared__ float t[32][33];
    const int bx = blockIdx.x << 5;   // n base
    const int by = blockIdx.y << 5;   // k base
#pragma unroll
    for (int j = 0; j < 32; j += 8)
        t[threadIdx.y + j][threadIdx.x] =
            W[(size_t)(by + threadIdx.y + j) * N + bx + threadIdx.x];
    __syncthreads();
#pragma unroll
    for (int j = 0; j < 32; j += 8) {
        float f = t[threadIdx.x][threadIdx.y + j] * SCALE_B;
        half h, l;
        split2(f, h, l);
        size_t o = (size_t)(bx + threadIdx.y + j) * HIDD + by + threadIdx.x;
        Th[o] = h;
        Tl[o] = l;
    }
}

// ---------------------------------------------------------------------------
// Fused centroid prep: tanh -> d_out, split halves, c2 sumsq, zero counts.
// ---------------------------------------------------------------------------
__global__ void centroid_prep(const float* __restrict__ raw, float* __restrict__ out)
{
    const int tid  = threadIdx.x;
    const int lane = tid & 31;
    const int row  = blockIdx.x * 8 + (tid >> 5);
    const int gtid = blockIdx.x * 256 + tid;
    if (gtid < 2 * KC) g_counts[gtid] = 0;

    const float* src = raw + (size_t)row * SEND;
    float ss = 0.0f;
#pragma unroll
    for (int j = 0; j < 8; ++j) {
        int idx = lane + j * 32;
        float t = tanhf(src[idx]);
        out[CENT_OFF + (size_t)row * SEND + idx] = t;
        half h, l;
        split2(t * SCALE_B, h, l);
        g_ch[(size_t)row * SEND + idx] = h;
        g_cl[(size_t)row * SEND + idx] = l;
        ss = fmaf(t, t, ss);
    }
#pragma unroll
    for (int o = 16; o > 0; o >>= 1) ss += __shfl_xor_sync(0xffffffffu, ss, o);
    if (lane == 0) g_c2[row] = ss;
}

// ---------------------------------------------------------------------------
// Counting sort (stable) — both modals per launch
// ---------------------------------------------------------------------------
__global__ void scan_kernel()
{
    __shared__ int tmp[KC];
    const int modal = blockIdx.x;
    int t = threadIdx.x;
    int v = g_counts[modal * KC + t];
    tmp[t] = v;
    __syncthreads();
    for (int off = 1; off < KC; off <<= 1) {
        int x = (t >= off) ? tmp[t - off] : 0;
        __syncthreads();
        tmp[t] += x;
        __syncthreads();
    }
    g_offsets[modal * KC + t] = tmp[t] - v;
}

__global__ void scatter_kernel(float* __restrict__ out)
{
    const int k = blockIdx.x;
    const int modal = blockIdx.y;
    float* order = out + (modal ? OI_OFF : OT_OFF);
    const int base0 = modal * NTOK;
    __shared__ int warpTot[8];
    int base = g_offsets[modal * KC + k];
    int lane = threadIdx.x & 31, wid = threadIdx.x >> 5;

    for (int start = 0; start < NTOK; start += 256) {
        int i = start + threadIdx.x;
        bool m = (g_sc[base0 + i] == k);
        unsigned b = __ballot_sync(0xffffffffu, m);
        if (lane == 0) warpTot[wid] = __popc(b);
        __syncthreads();
        int woff = 0, tot = 0;
#pragma unroll
        for (int w = 0; w < 8; ++w) { int c = warpTot[w]; tot += c; if (w < wid) woff += c; }
        if (m) order[base + woff + __popc(b & ((1u << lane) - 1u))] = (float)i;
        base += tot;
        __syncthreads();
    }
}

// ---------------------------------------------------------------------------
// word_class / sense_class / counts (fused)
// ---------------------------------------------------------------------------
__global__ void finalize_kernel(float* __restrict__ out)
{
    int i = blockIdx.x * blockDim.x + threadIdx.x;
    out[WC_OFF + i]  = (i < NTOK) ? 0.0f : 1.0f;
    out[SCL_OFF + i] = (float)g_sc[i];
    if (i < 2 * KC) {
        int m = i >> 9, k = i & 511;
        out[(m ? CI_OFF : CT_OFF) + k] = (float)g_counts[i];
    }
}

// ---------------------------------------------------------------------------
// Launch
// ---------------------------------------------------------------------------
extern "C" void kernel_launch(void* const* d_in, const int* in_sizes, int n_in,
                              void* d_out, int out_size)
{
    const float* emb[2] = { (const float*)d_in[0], (const float*)d_in[1] };
    const float* W1[2]  = { (const float*)d_in[2], (const float*)d_in[5] };
    const float* W2[2]  = { (const float*)d_in[3], (const float*)d_in[6] };
    const float* W3[2]  = { (const float*)d_in[4], (const float*)d_in[7] };
    const float* craw   = (const float*)d_in[8];
    float* out = (float*)d_out;

    half *xh1, *xl1, *xh2, *xl2;
    half *w1h, *w1l, *w2h, *w2l, *w3h, *w3l;
    float* e2p;
    cudaGetSymbolAddress((void**)&xh1, g_xh1);
    cudaGetSymbolAddress((void**)&xl1, g_xl1);
    cudaGetSymbolAddress((void**)&xh2, g_xh2);
    cudaGetSymbolAddress((void**)&xl2, g_xl2);
    cudaGetSymbolAddress((void**)&w1h, g_w1h);
    cudaGetSymbolAddress((void**)&w1l, g_w1l);
    cudaGetSymbolAddress((void**)&w2h, g_w2h);
    cudaGetSymbolAddress((void**)&w2l, g_w2l);
    cudaGetSymbolAddress((void**)&w3h, g_w3h);
    cudaGetSymbolAddress((void**)&w3l, g_w3l);
    cudaGetSymbolAddress((void**)&e2p, g_e2p);

    cudaFuncSetAttribute(gemm_split<1>,
                         cudaFuncAttributeMaxDynamicSharedMemorySize, GEMM_SMEM);
    cudaFuncSetAttribute(gemm_split<2>,
                         cudaFuncAttributeMaxDynamicSharedMemorySize, GEMM_SMEM);
    cudaFuncSetAttribute(assign_mma,
                         cudaFuncAttributeMaxDynamicSharedMemorySize, ASSIGN_SMEM);

    const size_t WSZ  = (size_t)HIDD * HIDD;
    const size_t W3SZ = (size_t)SEND * HIDD;

    centroid_prep<<<KC / 8, 256>>>(craw, out);
    transpose_split_all<<<dim3(32, 32, 6), dim3(32, 8)>>>(
        W1[0], W2[0], W3[0], W1[1], W2[1], W3[1]);

    split_src<<<dim3((NTOK * TOKD / 4) / 256, 2), 256>>>(emb[0], emb[1], xh1, xl1);

    // L1: xh1 -> xh2 (both modals)
    gemm_split<1><<<dim3(HIDD / 128, NTOK / 128, 2), 256, GEMM_SMEM>>>(
        xh1, xl1, ASLAB, w1h, w1l, WSZ,
        nullptr, 0, xh2, xl2, ASLAB, nullptr, TOKD, HIDD);

    // L2: xh2 -> xh1
    gemm_split<1><<<dim3(HIDD / 128, NTOK / 128, 2), 256, GEMM_SMEM>>>(
        xh2, xl2, ASLAB, w2h, w2l, WSZ,
        nullptr, 0, xh1, xl1, ASLAB, nullptr, HIDD, HIDD);

    // L3: xh1 -> se (fp32) + xh2 (split) + e2 partials
    gemm_split<2><<<dim3(SEND / 128, NTOK / 128, 2), 256, GEMM_SMEM>>>(
        xh1, xl1, ASLAB, w3h, w3l, W3SZ,
        out + SE_OFF, (size_t)NTOK * SEND, xh2, xl2, ASLAB, e2p, HIDD, SEND);

    assign_mma<<<dim3(NTOK / 128, 2), 256, ASSIGN_SMEM>>>(xh2, xl2);

    scan_kernel<<<2, KC>>>();
    scatter_kernel<<<dim3(KC, 2), 256>>>(out);

    finalize_kernel<<<(2 * NTOK) / 256, 256>>>(out);
}